// round 15
// baseline (speedup 1.0000x reference)
#include <cuda_runtime.h>
#include <cstdint>

// Problem constants
#define Bq 2
#define Sq 2048
#define Eq 1024
#define Hq 16
#define Dq 64
#define KKq 409           // max(1, int(S*0.2))
#define SCOREMUL 0.15625f // (1/sqrt(64)) / temperature, temperature = 0.8
#define DIAGMUL  1.15f    // 1 + ACH*0.3
#define MASKMUL  1.15f    // 1 + (-DA)*0.3

#define TM 16             // query rows per attention block
#define RS 2052           // sc row stride (floats)
#define WSL 1152          // u32 per warp staging slice
#define CCAP 896          // compaction buffer capacity (WSL - 256 hist bins)

// ---------------------------------------------------------------------------
// Scratch (device globals)
// ---------------------------------------------------------------------------
__device__ float    g_Q [Bq*Hq*Sq*Dq];   // (b,h,s,d)
__device__ float    g_V [Bq*Hq*Sq*Dq];   // (b,h,s,d)
__device__ float    g_O [Bq*Sq*Eq];      // (b,s,e)
__device__ float    g_Wt[4*Eq*Eq];       // Wq^T, Wk^T, Wv^T, Wo^T
__device__ uint32_t g_Kbh[Bq*Hq*Sq*32];  // K bf16 hi, (bh, s, d2)
__device__ uint32_t g_Kbl[Bq*Hq*Sq*32];  // K bf16 lo
__device__ uint32_t g_Vbh[Bq*Hq*Dq*1024];// V bf16 hi, (bh, d, s2)
__device__ uint32_t g_Vbl[Bq*Hq*Dq*1024];// V bf16 lo

// ---------------------------------------------------------------------------
// helpers
// ---------------------------------------------------------------------------
__device__ __forceinline__ uint32_t bfpack(float lo, float hi) {
    uint32_t r;
    asm("cvt.rn.bf16x2.f32 %0, %1, %2;" : "=r"(r) : "f"(hi), "f"(lo));
    return r;
}
__device__ __forceinline__ float bflowf(uint32_t p)  { return __uint_as_float(p << 16); }
__device__ __forceinline__ float bfhighf(uint32_t p) { return __uint_as_float(p & 0xFFFF0000u); }

__device__ __forceinline__ void mma_bf16(float* d, const uint32_t* a, uint32_t b0, uint32_t b1) {
    asm volatile(
        "mma.sync.aligned.m16n8k16.row.col.f32.bf16.bf16.f32 "
        "{%0,%1,%2,%3}, {%4,%5,%6,%7}, {%8,%9}, {%0,%1,%2,%3};"
        : "+f"(d[0]), "+f"(d[1]), "+f"(d[2]), "+f"(d[3])
        : "r"(a[0]), "r"(a[1]), "r"(a[2]), "r"(a[3]), "r"(b0), "r"(b1));
}

__device__ __forceinline__ unsigned fmap(float f) {
    unsigned u = __float_as_uint(f);
    return (u & 0x80000000u) ? ~u : (u | 0x80000000u);
}

__device__ __forceinline__ uint32_t smem_u32(const void* p) {
    uint32_t a;
    asm("{ .reg .u64 t; cvta.to.shared.u64 t, %1; cvt.u32.u64 %0, t; }" : "=r"(a) : "l"(p));
    return a;
}
__device__ __forceinline__ void cpa16(uint32_t dst, const void* src) {
    asm volatile("cp.async.cg.shared.global [%0], [%1], 16;" :: "r"(dst), "l"(src) : "memory");
}
#define CPA_COMMIT() asm volatile("cp.async.commit_group;" ::: "memory")
#define CPA_WAIT1()  asm volatile("cp.async.wait_group 1;" ::: "memory")
#define CPA_WAIT0()  asm volatile("cp.async.wait_group 0;" ::: "memory")

// warp radix-select step
__device__ __forceinline__ void radix_pick(const unsigned* hw, int lane, int kneed,
                                           int& bsel, int& nk, int& bcnt) {
    const int b0 = (31 - lane) * 8;
    unsigned cb[8], cl = 0;
    #pragma unroll
    for (int j = 0; j < 8; ++j) { cb[j] = hw[b0 + j]; cl += cb[j]; }
    unsigned S = cl;
    #pragma unroll
    for (int o = 1; o < 32; o <<= 1) {
        unsigned x = __shfl_up_sync(0xFFFFFFFFu, S, o);
        if (lane >= o) S += x;
    }
    unsigned excl = S - cl;
    bool has = (excl < (unsigned)kneed) && ((unsigned)kneed <= S);
    unsigned bal = __ballot_sync(0xFFFFFFFFu, has);
    int src = __ffs(bal) - 1;
    int bs = 0, n = 0, c = 0;
    if (lane == src) {
        int rem = kneed - (int)excl;
        #pragma unroll
        for (int j = 7; j >= 0; --j) {
            int cnt = (int)cb[j];
            if (rem <= cnt) { bs = b0 + j; n = rem; c = cnt; break; }
            rem -= cnt;
        }
    }
    bsel = __shfl_sync(0xFFFFFFFFu, bs, src);
    nk   = __shfl_sync(0xFFFFFFFFu, n, src);
    bcnt = __shfl_sync(0xFFFFFFFFu, c, src);
}

// ---------------------------------------------------------------------------
// Weight transpose: g_Wt[z] = W(z)^T
// ---------------------------------------------------------------------------
__global__ void wtrans_kernel(const float* __restrict__ Wq, const float* __restrict__ Wk,
                              const float* __restrict__ Wv, const float* __restrict__ Wo)
{
    __shared__ float t[32][33];
    const int z = blockIdx.z;
    const float* W = (z == 0) ? Wq : (z == 1) ? Wk : (z == 2) ? Wv : Wo;
    float* out = g_Wt + (size_t)z * Eq * Eq;
    const int x0 = blockIdx.x * 32, y0 = blockIdx.y * 32;
    const int tx = threadIdx.x, ty = threadIdx.y;
    #pragma unroll
    for (int i = 0; i < 32; i += 8)
        t[ty + i][tx] = W[(size_t)(y0 + ty + i) * Eq + x0 + tx];
    __syncthreads();
    #pragma unroll
    for (int i = 0; i < 32; i += 8)
        out[(size_t)(x0 + ty + i) * Eq + y0 + tx] = t[tx][ty + i];
}

// ---------------------------------------------------------------------------
// Convert V fp32 -> bf16 hi/lo (bh, d, s2)
// ---------------------------------------------------------------------------
__global__ __launch_bounds__(256) void conv_v_kernel()
{
    const int i = blockIdx.x * 256 + threadIdx.x;
    const int bh = i >> 16, rem = i & 65535;
    const int d = rem >> 10, s2 = rem & 1023;
    float v0 = g_V[(((size_t)(bh << 11) + 2 * s2)     << 6) + d];
    float v1 = g_V[(((size_t)(bh << 11) + 2 * s2 + 1) << 6) + d];
    uint32_t hh = bfpack(v0, v1);
    g_Vbh[i] = hh;
    g_Vbl[i] = bfpack(v0 - bflowf(hh), v1 - bfhighf(hh));
}

// ---------------------------------------------------------------------------
// bf16x3 mma GEMM core (validated)
// ---------------------------------------------------------------------------
#define SROW 20

__device__ __forceinline__ void gemm_core(
    const float* __restrict__ A, const float* __restrict__ Bt,
    uint32_t* Ahi, uint32_t* Alo, uint32_t* Bhi, uint32_t* Blo,
    int m0, int n0, float acc[2][8][4])
{
    const int tid  = threadIdx.x;
    const int wid  = tid >> 5, lane = tid & 31;
    const int gid  = lane >> 2, tig = lane & 3;
    const int wm   = wid & 3,  wn  = wid >> 2;

    const float4* pa[4];
    const float4* pb[4];
    int so[4];
    #pragma unroll
    for (int j = 0; j < 4; ++j) {
        int f4  = tid + j * 256;
        int row = f4 >> 3;
        int cq  = f4 & 7;
        pa[j] = (const float4*)(A  + (size_t)(m0 + row) * Eq) + cq;
        pb[j] = (const float4*)(Bt + (size_t)(n0 + row) * Eq) + cq;
        so[j] = row * SROW + cq * 2;
    }

    float4 ra[4], rb[4];
    #pragma unroll
    for (int j = 0; j < 4; ++j) { ra[j] = pa[j][0]; rb[j] = pb[j][0]; }

    for (int kc = 0; kc < 32; ++kc) {
        __syncthreads();
        #pragma unroll
        for (int j = 0; j < 4; ++j) {
            uint32_t h0 = bfpack(ra[j].x, ra[j].y);
            uint32_t h1 = bfpack(ra[j].z, ra[j].w);
            Ahi[so[j]]     = h0;
            Ahi[so[j] + 1] = h1;
            Alo[so[j]]     = bfpack(ra[j].x - bflowf(h0), ra[j].y - bfhighf(h0));
            Alo[so[j] + 1] = bfpack(ra[j].z - bflowf(h1), ra[j].w - bfhighf(h1));
            uint32_t g0 = bfpack(rb[j].x, rb[j].y);
            uint32_t g1 = bfpack(rb[j].z, rb[j].w);
            Bhi[so[j]]     = g0;
            Bhi[so[j] + 1] = g1;
            Blo[so[j]]     = bfpack(rb[j].x - bflowf(g0), rb[j].y - bfhighf(g0));
            Blo[so[j] + 1] = bfpack(rb[j].z - bflowf(g1), rb[j].w - bfhighf(g1));
        }
        __syncthreads();

        if (kc < 31) {
            #pragma unroll
            for (int j = 0; j < 4; ++j) {
                ra[j] = pa[j][(kc + 1) * 8];
                rb[j] = pb[j][(kc + 1) * 8];
            }
        }

        #pragma unroll
        for (int ks = 0; ks < 2; ++ks) {
            const int kb = ks * 8;
            uint32_t ah[2][4], al[2][4];
            #pragma unroll
            for (int mt = 0; mt < 2; ++mt) {
                const int r0 = wm * 32 + mt * 16 + gid;
                ah[mt][0] = Ahi[r0 * SROW + kb + tig];
                ah[mt][1] = Ahi[(r0 + 8) * SROW + kb + tig];
                ah[mt][2] = Ahi[r0 * SROW + kb + tig + 4];
                ah[mt][3] = Ahi[(r0 + 8) * SROW + kb + tig + 4];
                al[mt][0] = Alo[r0 * SROW + kb + tig];
                al[mt][1] = Alo[(r0 + 8) * SROW + kb + tig];
                al[mt][2] = Alo[r0 * SROW + kb + tig + 4];
                al[mt][3] = Alo[(r0 + 8) * SROW + kb + tig + 4];
            }
            #pragma unroll
            for (int nt = 0; nt < 8; ++nt) {
                const int n = wn * 64 + nt * 8 + gid;
                uint32_t bh0 = Bhi[n * SROW + kb + tig];
                uint32_t bh1 = Bhi[n * SROW + kb + tig + 4];
                uint32_t bl0 = Blo[n * SROW + kb + tig];
                uint32_t bl1 = Blo[n * SROW + kb + tig + 4];
                #pragma unroll
                for (int mt = 0; mt < 2; ++mt) {
                    mma_bf16(acc[mt][nt], ah[mt], bh0, bh1);
                    mma_bf16(acc[mt][nt], ah[mt], bl0, bl1);
                    mma_bf16(acc[mt][nt], al[mt], bh0, bh1);
                }
            }
        }
    }
}

// ---------------------------------------------------------------------------
// Fused QKV GEMM:
//   mode 0: query@Wq -> g_Q (b,h,s,d) +bq
//   mode 1: key@Wk   -> g_Kbh/l bf16 (bh,s,d2), (+bk)*ts[h]
//   mode 2: value@Wv -> g_V (b,h,s,d) +bv
// ---------------------------------------------------------------------------
__global__ __launch_bounds__(256, 2) void gemm_qkv_kernel(
    const float* __restrict__ query, const float* __restrict__ key,
    const float* __restrict__ value, const float* __restrict__ wt,
    const float* __restrict__ bq, const float* __restrict__ bk,
    const float* __restrict__ bv, const float* __restrict__ ts)
{
    __shared__ uint32_t sb[4 * 128 * SROW];
    const int mode = blockIdx.z;
    const float* A    = (mode == 0) ? query : (mode == 1) ? key : value;
    const float* Bt   = wt + (size_t)mode * Eq * Eq;
    const float* bias = (mode == 0) ? bq : (mode == 1) ? bk : bv;

    const int tid = threadIdx.x;
    const int wid = tid >> 5, lane = tid & 31;
    const int gid = lane >> 2, tig = lane & 3;
    const int wm  = wid & 3,  wn  = wid >> 2;
    const int m0  = blockIdx.y * 128, n0 = blockIdx.x * 128;

    float acc[2][8][4];
    #pragma unroll
    for (int mt = 0; mt < 2; ++mt)
        #pragma unroll
        for (int nt = 0; nt < 8; ++nt)
            #pragma unroll
            for (int c = 0; c < 4; ++c) acc[mt][nt][c] = 0.0f;

    gemm_core(A, Bt, sb, sb + 128 * SROW, sb + 2 * 128 * SROW, sb + 3 * 128 * SROW,
              m0, n0, acc);

    #pragma unroll
    for (int mt = 0; mt < 2; ++mt) {
        const int row = m0 + wm * 32 + mt * 16 + gid;
        const int bb = row >> 11, s = row & (Sq - 1);
        #pragma unroll
        for (int nt = 0; nt < 8; ++nt) {
            const int col = n0 + wn * 64 + nt * 8 + 2 * tig;
            const int h = col >> 6, dd = col & 63;
            const float* d = acc[mt][nt];
            float2 bvv = *(const float2*)(bias + col);
            if (mode == 1) {
                const float tv = ts[h];
                float v0 = (d[0] + bvv.x) * tv, v1 = (d[1] + bvv.y) * tv;
                float v2 = (d[2] + bvv.x) * tv, v3 = (d[3] + bvv.y) * tv;
                size_t idx = ((size_t)(bb * Hq + h) << 16) + s * 32 + (dd >> 1);
                uint32_t h0 = bfpack(v0, v1);
                g_Kbh[idx] = h0;
                g_Kbl[idx] = bfpack(v0 - bflowf(h0), v1 - bfhighf(h0));
                uint32_t h1 = bfpack(v2, v3);
                g_Kbh[idx + 256] = h1;
                g_Kbl[idx + 256] = bfpack(v2 - bflowf(h1), v3 - bfhighf(h1));
            } else {
                float* base = (mode == 0) ? g_Q : g_V;
                float* dst = base + ((size_t)(bb * Hq + h) * Sq + s) * Dq + dd;
                *(float2*)(dst)          = make_float2(d[0] + bvv.x, d[1] + bvv.y);
                *(float2*)(dst + 8 * Dq) = make_float2(d[2] + bvv.x, d[3] + bvv.y);
            }
        }
    }
}

// ---------------------------------------------------------------------------
// Output GEMM: d_out = g_O @ Wo + bo
// ---------------------------------------------------------------------------
__global__ __launch_bounds__(256, 2) void gemm_out_kernel(
    const float* __restrict__ wt, const float* __restrict__ bo,
    float* __restrict__ Cout)
{
    __shared__ uint32_t sb[4 * 128 * SROW];
    const int tid = threadIdx.x;
    const int wid = tid >> 5, lane = tid & 31;
    const int gid = lane >> 2, tig = lane & 3;
    const int wm  = wid & 3,  wn  = wid >> 2;
    const int m0  = blockIdx.y * 128, n0 = blockIdx.x * 128;

    float acc[2][8][4];
    #pragma unroll
    for (int mt = 0; mt < 2; ++mt)
        #pragma unroll
        for (int nt = 0; nt < 8; ++nt)
            #pragma unroll
            for (int c = 0; c < 4; ++c) acc[mt][nt][c] = 0.0f;

    gemm_core(g_O, wt + 3 * (size_t)Eq * Eq,
              sb, sb + 128 * SROW, sb + 2 * 128 * SROW, sb + 3 * 128 * SROW,
              m0, n0, acc);

    #pragma unroll
    for (int mt = 0; mt < 2; ++mt) {
        const int row = m0 + wm * 32 + mt * 16 + gid;
        #pragma unroll
        for (int nt = 0; nt < 8; ++nt) {
            const int col = n0 + wn * 64 + nt * 8 + 2 * tig;
            const float* d = acc[mt][nt];
            float2 bvv = *(const float2*)(bo + col);
            *(float2*)(Cout + (size_t)row * Eq + col) =
                make_float2(d[0] + bvv.x, d[1] + bvv.y);
            *(float2*)(Cout + (size_t)(row + 8) * Eq + col) =
                make_float2(d[2] + bvv.x, d[3] + bvv.y);
        }
    }
}

// ---------------------------------------------------------------------------
// Fused attention v12: R12 pipeline, with the pass-1 histogram folded into
// the QK epilogue (block-wide hist16[16][256]); the middle phase starts at
// radix_pick directly. Bit-identical threshold, one full scan deleted.
// ---------------------------------------------------------------------------
#define OFF_ST     (TM * RS)               // 32832
#define OFF_Q      (OFF_ST + 18432)        // 51264
#define OFF_INV    (OFF_Q + 16*66)         // 52320
#define OFF_WMAX   (OFF_INV + 16)          // 52336
#define OFF_HIST16 (OFF_WMAX + 256)        // 52592
#define SMEM_FLOATS (OFF_HIST16 + 4096)    // 56688 -> 226,752 B

__global__ __launch_bounds__(512, 1) void attn_kernel()
{
    extern __shared__ float smem[];
    float*    sc     = smem;
    uint32_t* sc_u   = (uint32_t*)smem;
    uint32_t* ST     = (uint32_t*)(smem + OFF_ST);
    float*    Qs     = smem + OFF_Q;
    float*    inv    = smem + OFF_INV;
    float*    wmax   = smem + OFF_WMAX;
    unsigned* hist16 = (unsigned*)(smem + OFF_HIST16);   // [16 rows][256 bins]

    const int tid = threadIdx.x;
    const int w   = tid >> 5, lane = tid & 31;
    const int gid = lane >> 2, tig = lane & 3;
    const int bh  = blockIdx.y;
    const int t0  = blockIdx.x * TM;
    const int b   = bh >> 4, h = bh & 15;

    const float* Qg = g_Q + (size_t)bh * Sq * Dq;
    const uint4* Kb4[2] = { (const uint4*)(g_Kbh + ((size_t)bh << 16)),
                            (const uint4*)(g_Kbl + ((size_t)bh << 16)) };
    const uint4* Vb4[2] = { (const uint4*)(g_Vbh + ((size_t)bh << 16)),
                            (const uint4*)(g_Vbl + ((size_t)bh << 16)) };

    const uint32_t* Wbuf = ST + w * WSL;
    const uint32_t wb_b  = smem_u32(ST) + ((w * WSL) << 2);

    int sarr[4], srr[4], sq[4];
    #pragma unroll
    for (int k = 0; k < 4; ++k) {
        int idx = lane + k * 32;
        sarr[k] = idx >> 6;
        srr[k]  = (idx >> 3) & 7;
        sq[k]   = idx & 7;
    }
    const int nd = w & 7, kh = w >> 3;

    // ---- prefetch K chunk 0 ----
    #pragma unroll
    for (int k = 0; k < 4; ++k)
        cpa16(wb_b + ((sarr[k] * 288 + srr[k] * 36 + sq[k] * 4) << 2),
              Kb4[sarr[k]] + ((w * 8 + srr[k]) * 8 + sq[k]));
    CPA_COMMIT();

    // ---- Q stage + zero hist16 ----
    for (int i = tid; i < TM * Dq; i += 512) {
        int r = i >> 6, d = i & 63;
        Qs[r * 66 + d] = Qg[(size_t)(t0 + r) * Dq + d];
    }
    for (int i = tid; i < 4096; i += 512) hist16[i] = 0;
    __syncthreads();

    // ---- Q fragments ----
    uint32_t ahq[4][4], alq[4][4];
    #pragma unroll
    for (int ks = 0; ks < 4; ++ks) {
        float2 q[4];
        q[0] = *(float2*)&Qs[gid * 66 + ks * 16 + 2 * tig];
        q[1] = *(float2*)&Qs[(gid + 8) * 66 + ks * 16 + 2 * tig];
        q[2] = *(float2*)&Qs[gid * 66 + ks * 16 + 2 * tig + 8];
        q[3] = *(float2*)&Qs[(gid + 8) * 66 + ks * 16 + 2 * tig + 8];
        #pragma unroll
        for (int j = 0; j < 4; ++j) {
            uint32_t hh = bfpack(q[j].x, q[j].y);
            ahq[ks][j] = hh;
            alq[ks][j] = bfpack(q[j].x - bflowf(hh), q[j].y - bfhighf(hh));
        }
    }

    // ---- QK^T: 16 chunks, track row max + inline pass-1 histogram ----
    float mx0 = -3.402823466e+38f, mx1 = -3.402823466e+38f;

    for (int c = 0; c < 16; ++c) {
        const int buf = c & 1;
        if (c < 15) {
            const int bo2 = (buf ^ 1) * 576;
            #pragma unroll
            for (int k = 0; k < 4; ++k)
                cpa16(wb_b + ((bo2 + sarr[k] * 288 + srr[k] * 36 + sq[k] * 4) << 2),
                      Kb4[sarr[k]] + (((c + 1) * 128 + w * 8 + srr[k]) * 8 + sq[k]));
            CPA_COMMIT();
            CPA_WAIT1();
        } else {
            CPA_WAIT0();
        }
        __syncwarp();

        const uint32_t* KH = Wbuf + buf * 576;
        const uint32_t* KL = KH + 288;
        float cf[4] = {0.f, 0.f, 0.f, 0.f};
        #pragma unroll
        for (int ks = 0; ks < 4; ++ks) {
            uint32_t b0h = KH[gid * 36 + ks * 8 + tig];
            uint32_t b1h = KH[gid * 36 + ks * 8 + 4 + tig];
            uint32_t b0l = KL[gid * 36 + ks * 8 + tig];
            uint32_t b1l = KL[gid * 36 + ks * 8 + 4 + tig];
            mma_bf16(cf, ahq[ks], b0h, b1h);
            mma_bf16(cf, ahq[ks], b0l, b1l);
            mma_bf16(cf, alq[ks], b0h, b1h);
        }
        const int sg = (c << 7) + w * 8 + 2 * tig;
        float v0 = cf[0] * SCOREMUL; if (sg     == t0 + gid)     v0 *= DIAGMUL;
        float v1 = cf[1] * SCOREMUL; if (sg + 1 == t0 + gid)     v1 *= DIAGMUL;
        float v2 = cf[2] * SCOREMUL; if (sg     == t0 + gid + 8) v2 *= DIAGMUL;
        float v3 = cf[3] * SCOREMUL; if (sg + 1 == t0 + gid + 8) v3 *= DIAGMUL;
        mx0 = fmaxf(mx0, fmaxf(v0, v1));
        mx1 = fmaxf(mx1, fmaxf(v2, v3));
        // inline pass-1 histogram (post-diag values, pre-mask): bit-identical
        atomicAdd(&hist16[gid * 256       + (fmap(v0) >> 24)], 1u);
        atomicAdd(&hist16[gid * 256       + (fmap(v1) >> 24)], 1u);
        atomicAdd(&hist16[(gid + 8) * 256 + (fmap(v2) >> 24)], 1u);
        atomicAdd(&hist16[(gid + 8) * 256 + (fmap(v3) >> 24)], 1u);
        *(float2*)&sc[gid * RS + sg]       = make_float2(v0, v1);
        *(float2*)&sc[(gid + 8) * RS + sg] = make_float2(v2, v3);
        __syncwarp();
    }
    mx0 = fmaxf(mx0, __shfl_xor_sync(0xFFFFFFFFu, mx0, 1));
    mx0 = fmaxf(mx0, __shfl_xor_sync(0xFFFFFFFFu, mx0, 2));
    mx1 = fmaxf(mx1, __shfl_xor_sync(0xFFFFFFFFu, mx1, 1));
    mx1 = fmaxf(mx1, __shfl_xor_sync(0xFFFFFFFFu, mx1, 2));
    if (tig == 0) {
        wmax[w * 16 + gid]     = mx0;
        wmax[w * 16 + gid + 8] = mx1;
    }
    __syncthreads();   // all scores + maxes + histograms complete

    // ---- middle (one warp per row): radix_pick -> compact -> passes 2-4 ----
    {
        const int r = w;
        unsigned* hw   = (unsigned*)(ST + w * WSL);
        unsigned* cbuf = (unsigned*)(ST + w * WSL) + 256;

        float tmx = (lane < 16) ? wmax[lane * 16 + r] : -3.402823466e+38f;
        #pragma unroll
        for (int o = 8; o; o >>= 1) tmx = fmaxf(tmx, __shfl_xor_sync(0xFFFFFFFFu, tmx, o));
        tmx = __shfl_sync(0xFFFFFFFFu, tmx, 0);
        const float M = (tmx > 0.0f) ? tmx * MASKMUL : tmx;

        // pass 1 result comes from hist16 (filled during QK)
        int bsel, nk, bcnt;
        radix_pick(hist16 + r * 256, lane, KKq, bsel, nk, bcnt);
        unsigned thrp = ((unsigned)bsel) << 24;
        int kneed = nk;
        __syncwarp();

        if (bcnt <= CCAP) {
            // ---- compact the selected top-byte bucket ----
            const unsigned pb = thrp >> 24;
            int nc = 0;
            for (int j = 0; j < 16; ++j) {
                float4 v4 = *(const float4*)&sc[r * RS + ((j * 32 + lane) << 2)];
                unsigned u[4] = { fmap(v4.x), fmap(v4.y), fmap(v4.z), fmap(v4.w) };
                #pragma unroll
                for (int e = 0; e < 4; ++e) {
                    bool ok = (u[e] >> 24) == pb;
                    unsigned bal = __ballot_sync(0xFFFFFFFFu, ok);
                    if (ok)
                        cbuf[nc + __popc(bal & ((1u << lane) - 1u))] = u[e];
                    nc += __popc(bal);
                }
            }
            __syncwarp();
            for (int shift = 16; shift >= 0; shift -= 8) {
                #pragma unroll
                for (int j = 0; j < 8; ++j) hw[lane + j * 32] = 0;
                __syncwarp();
                for (int i = lane; i < nc; i += 32) {
                    unsigned u = cbuf[i];
                    if (((u ^ thrp) >> (shift + 8)) == 0)
                        atomicAdd(&hw[(u >> shift) & 255], 1u);
                }
                __syncwarp();
                radix_pick(hw, lane, kneed, bsel, nk, bcnt);
                thrp |= ((unsigned)bsel) << shift;
                kneed = nk;
                __syncwarp();
            }
        } else {
            // ---- fallback: full scans ----
            for (int shift = 16; shift >= 0; shift -= 8) {
                #pragma unroll
                for (int j = 0; j < 8; ++j) hw[lane + j * 32] = 0;
                __syncwarp();
                for (int j = 0; j < 16; ++j) {
                    float4 v4 = *(const float4*)&sc[r * RS + ((j * 32 + lane) << 2)];
                    unsigned u0 = fmap(v4.x), u1 = fmap(v4.y);
                    unsigned u2 = fmap(v4.z), u3 = fmap(v4.w);
                    if (((u0 ^ thrp) >> (shift + 8)) == 0) atomicAdd(&hw[(u0 >> shift) & 255], 1u);
                    if (((u1 ^ thrp) >> (shift + 8)) == 0) atomicAdd(&hw[(u1 >> shift) & 255], 1u);
                    if (((u2 ^ thrp) >> (shift + 8)) == 0) atomicAdd(&hw[(u2 >> shift) & 255], 1u);
                    if (((u3 ^ thrp) >> (shift + 8)) == 0) atomicAdd(&hw[(u3 >> shift) & 255], 1u);
                }
                __syncwarp();
                radix_pick(hw, lane, kneed, bsel, nk, bcnt);
                thrp |= ((unsigned)bsel) << shift;
                kneed = nk;
                __syncwarp();
            }
        }

        // ---- fused: boost + exp + sum + bf16 hi/lo pack ----
        float sum = 0.0f;
        for (int j = 0; j < 16; ++j) {
            const int base = r * RS + ((j * 32 + lane) << 2);
            float4 v4 = *(const float4*)&sc[base];
            float x0 = (fmap(v4.x) >= thrp) ? v4.x * MASKMUL : v4.x;
            float x1 = (fmap(v4.y) >= thrp) ? v4.y * MASKMUL : v4.y;
            float x2 = (fmap(v4.z) >= thrp) ? v4.z * MASKMUL : v4.z;
            float x3 = (fmap(v4.w) >= thrp) ? v4.w * MASKMUL : v4.w;
            float e0 = __expf(x0 - M);
            float e1 = __expf(x1 - M);
            float e2 = __expf(x2 - M);
            float e3 = __expf(x3 - M);
            sum += (e0 + e1) + (e2 + e3);
            uint32_t h0 = bfpack(e0, e1);
            uint32_t l0 = bfpack(e0 - bflowf(h0), e1 - bfhighf(h0));
            uint32_t h1 = bfpack(e2, e3);
            uint32_t l1 = bfpack(e2 - bflowf(h1), e3 - bfhighf(h1));
            uint4 pk; pk.x = h0; pk.y = l0; pk.z = h1; pk.w = l1;
            *(uint4*)&sc_u[base] = pk;
        }
        #pragma unroll
        for (int o = 16; o; o >>= 1) sum += __shfl_xor_sync(0xFFFFFFFFu, sum, o);
        if (lane == 0) inv[r] = 1.0f / sum;
    }

    // prefetch V chunk 0 into own slice
    #pragma unroll
    for (int k = 0; k < 4; ++k)
        cpa16(wb_b + ((sarr[k] * 288 + srr[k] * 36 + sq[k] * 4) << 2),
              Vb4[sarr[k]] + ((nd * 8 + srr[k]) * 256 + kh * 8 + sq[k]));
    CPA_COMMIT();
    __syncthreads();

    // ---- P @ V: 16 chunks of 128 s, warp-decoupled ----
    float cacc[4] = {0.f, 0.f, 0.f, 0.f};

    for (int c = 0; c < 16; ++c) {
        const int buf = c & 1;
        if (c < 15) {
            const int bo2 = (buf ^ 1) * 576;
            #pragma unroll
            for (int k = 0; k < 4; ++k)
                cpa16(wb_b + ((bo2 + sarr[k] * 288 + srr[k] * 36 + sq[k] * 4) << 2),
                      Vb4[sarr[k]] + ((nd * 8 + srr[k]) * 256 + (c + 1) * 16 + kh * 8 + sq[k]));
            CPA_COMMIT();
            CPA_WAIT1();
        } else {
            CPA_WAIT0();
        }
        __syncwarp();

        const uint32_t* VH = Wbuf + buf * 576;
        const uint32_t* VL = VH + 288;

        #pragma unroll
        for (int kk = 0; kk < 4; ++kk) {
            const int kp = kh * 4 + kk;
            const int k0 = (c << 7) + (kp << 4);
            uint2 A0 = *(uint2*)&sc_u[gid * RS + k0 + 2 * tig];
            uint2 A1 = *(uint2*)&sc_u[(gid + 8) * RS + k0 + 2 * tig];
            uint2 A2 = *(uint2*)&sc_u[gid * RS + k0 + 8 + 2 * tig];
            uint2 A3 = *(uint2*)&sc_u[(gid + 8) * RS + k0 + 8 + 2 * tig];
            uint32_t ah[4] = {A0.x, A1.x, A2.x, A3.x};
            uint32_t al[4] = {A0.y, A1.y, A2.y, A3.y};

            uint32_t b0h = VH[gid * 36 + kk * 8 + tig];
            uint32_t b1h = VH[gid * 36 + kk * 8 + 4 + tig];
            uint32_t b0l = VL[gid * 36 + kk * 8 + tig];
            uint32_t b1l = VL[gid * 36 + kk * 8 + 4 + tig];
            mma_bf16(cacc, ah, b0h, b1h);
            mma_bf16(cacc, ah, b0l, b1l);
            mma_bf16(cacc, al, b0h, b1h);
        }
        __syncwarp();
    }

    // ---- partials into own slice, reduce across kh, write g_O ----
    {
        float* PS = (float*)(ST + w * WSL);
        PS[gid * 8 + 2 * tig]           = cacc[0];
        PS[gid * 8 + 2 * tig + 1]       = cacc[1];
        PS[(gid + 8) * 8 + 2 * tig]     = cacc[2];
        PS[(gid + 8) * 8 + 2 * tig + 1] = cacc[3];
    }
    __syncthreads();

    {
        const float* PSb = (const float*)ST;
        for (int i = tid; i < TM * Dq; i += 512) {
            int r = i >> 6, d = i & 63;
            int n2 = d >> 3, dd = d & 7;
            float o = (PSb[(size_t)n2 * WSL + r * 8 + dd] +
                       PSb[(size_t)(8 + n2) * WSL + r * 8 + dd]) * inv[r];
            g_O[((size_t)(b * Sq + t0 + r)) * Eq + h * Dq + d] = o;
        }
    }
}

// ---------------------------------------------------------------------------
// Launch
// ---------------------------------------------------------------------------
extern "C" void kernel_launch(void* const* d_in, const int* in_sizes, int n_in,
                              void* d_out, int out_size)
{
    const float* query = (const float*)d_in[0];
    const float* key   = (const float*)d_in[1];
    const float* value = (const float*)d_in[2];
    const float* Wq    = (const float*)d_in[3];
    const float* bq    = (const float*)d_in[4];
    const float* Wk    = (const float*)d_in[5];
    const float* bk    = (const float*)d_in[6];
    const float* Wv    = (const float*)d_in[7];
    const float* bv    = (const float*)d_in[8];
    const float* Wo    = (const float*)d_in[9];
    const float* bo    = (const float*)d_in[10];
    const float* ts    = (const float*)d_in[11];

    cudaFuncSetAttribute(attn_kernel, cudaFuncAttributeMaxDynamicSharedMemorySize,
                         SMEM_FLOATS * 4);

    dim3 gT(Eq / 32, Eq / 32, 4);
    wtrans_kernel<<<gT, dim3(32, 8)>>>(Wq, Wk, Wv, Wo);

    float* wt; cudaGetSymbolAddress((void**)&wt, g_Wt);

    dim3 gQKV(Eq / 128, (Bq * Sq) / 128, 3);
    gemm_qkv_kernel<<<gQKV, 256>>>(query, key, value, wt, bq, bk, bv, ts);

    conv_v_kernel<<<8192, 256>>>();

    dim3 gAttn(Sq / TM, Bq * Hq);
    attn_kernel<<<gAttn, 512, SMEM_FLOATS * 4>>>();

    dim3 gO(Eq / 128, (Bq * Sq) / 128);
    gemm_out_kernel<<<gO, 256>>>(wt, bo, (float*)d_out);
}

// round 16
// speedup vs baseline: 1.1299x; 1.1299x over previous
#include <cuda_runtime.h>
#include <cstdint>

// Problem constants
#define Bq 2
#define Sq 2048
#define Eq 1024
#define Hq 16
#define Dq 64
#define KKq 409           // max(1, int(S*0.2))
#define SCOREMUL 0.15625f // (1/sqrt(64)) / temperature, temperature = 0.8
#define DIAGMUL  1.15f    // 1 + ACH*0.3
#define MASKMUL  1.15f    // 1 + (-DA)*0.3

#define TM 16             // query rows per attention block
#define RS 2056           // sc row stride (floats); 2056 % 32 == 8 -> conflict-free
#define WSL 1152          // u32 per warp staging slice
#define CCAP 896          // compaction buffer capacity (WSL - 256 hist bins)

// ---------------------------------------------------------------------------
// Scratch (device globals)
// ---------------------------------------------------------------------------
__device__ float    g_Q [Bq*Hq*Sq*Dq];   // (b,h,s,d)
__device__ float    g_V [Bq*Hq*Sq*Dq];   // (b,h,s,d)
__device__ float    g_O [Bq*Sq*Eq];      // (b,s,e)
__device__ float    g_Wt[4*Eq*Eq];       // Wq^T, Wk^T, Wv^T, Wo^T
__device__ uint32_t g_Kbh[Bq*Hq*Sq*32];  // K bf16 hi, (bh, s, d2)
__device__ uint32_t g_Kbl[Bq*Hq*Sq*32];  // K bf16 lo
__device__ uint32_t g_Vbh[Bq*Hq*Dq*1024];// V bf16 hi, (bh, d, s2)
__device__ uint32_t g_Vbl[Bq*Hq*Dq*1024];// V bf16 lo

// ---------------------------------------------------------------------------
// helpers
// ---------------------------------------------------------------------------
__device__ __forceinline__ uint32_t bfpack(float lo, float hi) {
    uint32_t r;
    asm("cvt.rn.bf16x2.f32 %0, %1, %2;" : "=r"(r) : "f"(hi), "f"(lo));
    return r;
}
__device__ __forceinline__ float bflowf(uint32_t p)  { return __uint_as_float(p << 16); }
__device__ __forceinline__ float bfhighf(uint32_t p) { return __uint_as_float(p & 0xFFFF0000u); }

__device__ __forceinline__ void mma_bf16(float* d, const uint32_t* a, uint32_t b0, uint32_t b1) {
    asm volatile(
        "mma.sync.aligned.m16n8k16.row.col.f32.bf16.bf16.f32 "
        "{%0,%1,%2,%3}, {%4,%5,%6,%7}, {%8,%9}, {%0,%1,%2,%3};"
        : "+f"(d[0]), "+f"(d[1]), "+f"(d[2]), "+f"(d[3])
        : "r"(a[0]), "r"(a[1]), "r"(a[2]), "r"(a[3]), "r"(b0), "r"(b1));
}

__device__ __forceinline__ unsigned fmap(float f) {
    unsigned u = __float_as_uint(f);
    return (u & 0x80000000u) ? ~u : (u | 0x80000000u);
}

__device__ __forceinline__ uint32_t smem_u32(const void* p) {
    uint32_t a;
    asm("{ .reg .u64 t; cvta.to.shared.u64 t, %1; cvt.u32.u64 %0, t; }" : "=r"(a) : "l"(p));
    return a;
}
__device__ __forceinline__ void cpa16(uint32_t dst, const void* src) {
    asm volatile("cp.async.cg.shared.global [%0], [%1], 16;" :: "r"(dst), "l"(src) : "memory");
}
#define CPA_COMMIT() asm volatile("cp.async.commit_group;" ::: "memory")
#define CPA_WAIT1()  asm volatile("cp.async.wait_group 1;" ::: "memory")
#define CPA_WAIT0()  asm volatile("cp.async.wait_group 0;" ::: "memory")

// warp radix-select step
__device__ __forceinline__ void radix_pick(const unsigned* hw, int lane, int kneed,
                                           int& bsel, int& nk, int& bcnt) {
    const int b0 = (31 - lane) * 8;
    unsigned cb[8], cl = 0;
    #pragma unroll
    for (int j = 0; j < 8; ++j) { cb[j] = hw[b0 + j]; cl += cb[j]; }
    unsigned S = cl;
    #pragma unroll
    for (int o = 1; o < 32; o <<= 1) {
        unsigned x = __shfl_up_sync(0xFFFFFFFFu, S, o);
        if (lane >= o) S += x;
    }
    unsigned excl = S - cl;
    bool has = (excl < (unsigned)kneed) && ((unsigned)kneed <= S);
    unsigned bal = __ballot_sync(0xFFFFFFFFu, has);
    int src = __ffs(bal) - 1;
    int bs = 0, n = 0, c = 0;
    if (lane == src) {
        int rem = kneed - (int)excl;
        #pragma unroll
        for (int j = 7; j >= 0; --j) {
            int cnt = (int)cb[j];
            if (rem <= cnt) { bs = b0 + j; n = rem; c = cnt; break; }
            rem -= cnt;
        }
    }
    bsel = __shfl_sync(0xFFFFFFFFu, bs, src);
    nk   = __shfl_sync(0xFFFFFFFFu, n, src);
    bcnt = __shfl_sync(0xFFFFFFFFu, c, src);
}

// ---------------------------------------------------------------------------
// Weight transpose: g_Wt[z] = W(z)^T
// ---------------------------------------------------------------------------
__global__ void wtrans_kernel(const float* __restrict__ Wq, const float* __restrict__ Wk,
                              const float* __restrict__ Wv, const float* __restrict__ Wo)
{
    __shared__ float t[32][33];
    const int z = blockIdx.z;
    const float* W = (z == 0) ? Wq : (z == 1) ? Wk : (z == 2) ? Wv : Wo;
    float* out = g_Wt + (size_t)z * Eq * Eq;
    const int x0 = blockIdx.x * 32, y0 = blockIdx.y * 32;
    const int tx = threadIdx.x, ty = threadIdx.y;
    #pragma unroll
    for (int i = 0; i < 32; i += 8)
        t[ty + i][tx] = W[(size_t)(y0 + ty + i) * Eq + x0 + tx];
    __syncthreads();
    #pragma unroll
    for (int i = 0; i < 32; i += 8)
        out[(size_t)(x0 + ty + i) * Eq + y0 + tx] = t[tx][ty + i];
}

// ---------------------------------------------------------------------------
// Convert V fp32 -> bf16 hi/lo (bh, d, s2)
// ---------------------------------------------------------------------------
__global__ __launch_bounds__(256) void conv_v_kernel()
{
    const int i = blockIdx.x * 256 + threadIdx.x;
    const int bh = i >> 16, rem = i & 65535;
    const int d = rem >> 10, s2 = rem & 1023;
    float v0 = g_V[(((size_t)(bh << 11) + 2 * s2)     << 6) + d];
    float v1 = g_V[(((size_t)(bh << 11) + 2 * s2 + 1) << 6) + d];
    uint32_t hh = bfpack(v0, v1);
    g_Vbh[i] = hh;
    g_Vbl[i] = bfpack(v0 - bflowf(hh), v1 - bfhighf(hh));
}

// ---------------------------------------------------------------------------
// bf16x3 mma GEMM core (validated)
// ---------------------------------------------------------------------------
#define SROW 20

__device__ __forceinline__ void gemm_core(
    const float* __restrict__ A, const float* __restrict__ Bt,
    uint32_t* Ahi, uint32_t* Alo, uint32_t* Bhi, uint32_t* Blo,
    int m0, int n0, float acc[2][8][4])
{
    const int tid  = threadIdx.x;
    const int wid  = tid >> 5, lane = tid & 31;
    const int gid  = lane >> 2, tig = lane & 3;
    const int wm   = wid & 3,  wn  = wid >> 2;

    const float4* pa[4];
    const float4* pb[4];
    int so[4];
    #pragma unroll
    for (int j = 0; j < 4; ++j) {
        int f4  = tid + j * 256;
        int row = f4 >> 3;
        int cq  = f4 & 7;
        pa[j] = (const float4*)(A  + (size_t)(m0 + row) * Eq) + cq;
        pb[j] = (const float4*)(Bt + (size_t)(n0 + row) * Eq) + cq;
        so[j] = row * SROW + cq * 2;
    }

    float4 ra[4], rb[4];
    #pragma unroll
    for (int j = 0; j < 4; ++j) { ra[j] = pa[j][0]; rb[j] = pb[j][0]; }

    for (int kc = 0; kc < 32; ++kc) {
        __syncthreads();
        #pragma unroll
        for (int j = 0; j < 4; ++j) {
            uint32_t h0 = bfpack(ra[j].x, ra[j].y);
            uint32_t h1 = bfpack(ra[j].z, ra[j].w);
            Ahi[so[j]]     = h0;
            Ahi[so[j] + 1] = h1;
            Alo[so[j]]     = bfpack(ra[j].x - bflowf(h0), ra[j].y - bfhighf(h0));
            Alo[so[j] + 1] = bfpack(ra[j].z - bflowf(h1), ra[j].w - bfhighf(h1));
            uint32_t g0 = bfpack(rb[j].x, rb[j].y);
            uint32_t g1 = bfpack(rb[j].z, rb[j].w);
            Bhi[so[j]]     = g0;
            Bhi[so[j] + 1] = g1;
            Blo[so[j]]     = bfpack(rb[j].x - bflowf(g0), rb[j].y - bfhighf(g0));
            Blo[so[j] + 1] = bfpack(rb[j].z - bflowf(g1), rb[j].w - bfhighf(g1));
        }
        __syncthreads();

        if (kc < 31) {
            #pragma unroll
            for (int j = 0; j < 4; ++j) {
                ra[j] = pa[j][(kc + 1) * 8];
                rb[j] = pb[j][(kc + 1) * 8];
            }
        }

        #pragma unroll
        for (int ks = 0; ks < 2; ++ks) {
            const int kb = ks * 8;
            uint32_t ah[2][4], al[2][4];
            #pragma unroll
            for (int mt = 0; mt < 2; ++mt) {
                const int r0 = wm * 32 + mt * 16 + gid;
                ah[mt][0] = Ahi[r0 * SROW + kb + tig];
                ah[mt][1] = Ahi[(r0 + 8) * SROW + kb + tig];
                ah[mt][2] = Ahi[r0 * SROW + kb + tig + 4];
                ah[mt][3] = Ahi[(r0 + 8) * SROW + kb + tig + 4];
                al[mt][0] = Alo[r0 * SROW + kb + tig];
                al[mt][1] = Alo[(r0 + 8) * SROW + kb + tig];
                al[mt][2] = Alo[r0 * SROW + kb + tig + 4];
                al[mt][3] = Alo[(r0 + 8) * SROW + kb + tig + 4];
            }
            #pragma unroll
            for (int nt = 0; nt < 8; ++nt) {
                const int n = wn * 64 + nt * 8 + gid;
                uint32_t bh0 = Bhi[n * SROW + kb + tig];
                uint32_t bh1 = Bhi[n * SROW + kb + tig + 4];
                uint32_t bl0 = Blo[n * SROW + kb + tig];
                uint32_t bl1 = Blo[n * SROW + kb + tig + 4];
                #pragma unroll
                for (int mt = 0; mt < 2; ++mt) {
                    mma_bf16(acc[mt][nt], ah[mt], bh0, bh1);
                    mma_bf16(acc[mt][nt], ah[mt], bl0, bl1);
                    mma_bf16(acc[mt][nt], al[mt], bh0, bh1);
                }
            }
        }
    }
}

// ---------------------------------------------------------------------------
// Fused QKV GEMM:
//   mode 0: query@Wq -> g_Q (b,h,s,d) +bq
//   mode 1: key@Wk   -> g_Kbh/l bf16 (bh,s,d2), (+bk)*ts[h]
//   mode 2: value@Wv -> g_V (b,h,s,d) +bv
// ---------------------------------------------------------------------------
__global__ __launch_bounds__(256, 2) void gemm_qkv_kernel(
    const float* __restrict__ query, const float* __restrict__ key,
    const float* __restrict__ value, const float* __restrict__ wt,
    const float* __restrict__ bq, const float* __restrict__ bk,
    const float* __restrict__ bv, const float* __restrict__ ts)
{
    __shared__ uint32_t sb[4 * 128 * SROW];
    const int mode = blockIdx.z;
    const float* A    = (mode == 0) ? query : (mode == 1) ? key : value;
    const float* Bt   = wt + (size_t)mode * Eq * Eq;
    const float* bias = (mode == 0) ? bq : (mode == 1) ? bk : bv;

    const int tid = threadIdx.x;
    const int wid = tid >> 5, lane = tid & 31;
    const int gid = lane >> 2, tig = lane & 3;
    const int wm  = wid & 3,  wn  = wid >> 2;
    const int m0  = blockIdx.y * 128, n0 = blockIdx.x * 128;

    float acc[2][8][4];
    #pragma unroll
    for (int mt = 0; mt < 2; ++mt)
        #pragma unroll
        for (int nt = 0; nt < 8; ++nt)
            #pragma unroll
            for (int c = 0; c < 4; ++c) acc[mt][nt][c] = 0.0f;

    gemm_core(A, Bt, sb, sb + 128 * SROW, sb + 2 * 128 * SROW, sb + 3 * 128 * SROW,
              m0, n0, acc);

    #pragma unroll
    for (int mt = 0; mt < 2; ++mt) {
        const int row = m0 + wm * 32 + mt * 16 + gid;
        const int bb = row >> 11, s = row & (Sq - 1);
        #pragma unroll
        for (int nt = 0; nt < 8; ++nt) {
            const int col = n0 + wn * 64 + nt * 8 + 2 * tig;
            const int h = col >> 6, dd = col & 63;
            const float* d = acc[mt][nt];
            float2 bvv = *(const float2*)(bias + col);
            if (mode == 1) {
                const float tv = ts[h];
                float v0 = (d[0] + bvv.x) * tv, v1 = (d[1] + bvv.y) * tv;
                float v2 = (d[2] + bvv.x) * tv, v3 = (d[3] + bvv.y) * tv;
                size_t idx = ((size_t)(bb * Hq + h) << 16) + s * 32 + (dd >> 1);
                uint32_t h0 = bfpack(v0, v1);
                g_Kbh[idx] = h0;
                g_Kbl[idx] = bfpack(v0 - bflowf(h0), v1 - bfhighf(h0));
                uint32_t h1 = bfpack(v2, v3);
                g_Kbh[idx + 256] = h1;
                g_Kbl[idx + 256] = bfpack(v2 - bflowf(h1), v3 - bfhighf(h1));
            } else {
                float* base = (mode == 0) ? g_Q : g_V;
                float* dst = base + ((size_t)(bb * Hq + h) * Sq + s) * Dq + dd;
                *(float2*)(dst)          = make_float2(d[0] + bvv.x, d[1] + bvv.y);
                *(float2*)(dst + 8 * Dq) = make_float2(d[2] + bvv.x, d[3] + bvv.y);
            }
        }
    }
}

// ---------------------------------------------------------------------------
// Output GEMM: d_out = g_O @ Wo + bo
// ---------------------------------------------------------------------------
__global__ __launch_bounds__(256, 2) void gemm_out_kernel(
    const float* __restrict__ wt, const float* __restrict__ bo,
    float* __restrict__ Cout)
{
    __shared__ uint32_t sb[4 * 128 * SROW];
    const int tid = threadIdx.x;
    const int wid = tid >> 5, lane = tid & 31;
    const int gid = lane >> 2, tig = lane & 3;
    const int wm  = wid & 3,  wn  = wid >> 2;
    const int m0  = blockIdx.y * 128, n0 = blockIdx.x * 128;

    float acc[2][8][4];
    #pragma unroll
    for (int mt = 0; mt < 2; ++mt)
        #pragma unroll
        for (int nt = 0; nt < 8; ++nt)
            #pragma unroll
            for (int c = 0; c < 4; ++c) acc[mt][nt][c] = 0.0f;

    gemm_core(g_O, wt + 3 * (size_t)Eq * Eq,
              sb, sb + 128 * SROW, sb + 2 * 128 * SROW, sb + 3 * 128 * SROW,
              m0, n0, acc);

    #pragma unroll
    for (int mt = 0; mt < 2; ++mt) {
        const int row = m0 + wm * 32 + mt * 16 + gid;
        #pragma unroll
        for (int nt = 0; nt < 8; ++nt) {
            const int col = n0 + wn * 64 + nt * 8 + 2 * tig;
            const float* d = acc[mt][nt];
            float2 bvv = *(const float2*)(bo + col);
            *(float2*)(Cout + (size_t)row * Eq + col) =
                make_float2(d[0] + bvv.x, d[1] + bvv.y);
            *(float2*)(Cout + (size_t)(row + 8) * Eq + col) =
                make_float2(d[2] + bvv.x, d[3] + bvv.y);
        }
    }
}

// ---------------------------------------------------------------------------
// Fused attention (R12 pipeline, RS=2056 conflict-free score stride)
// ---------------------------------------------------------------------------
#define OFF_ST   (TM * RS)               // 32896
#define OFF_Q    (OFF_ST + 18432)        // 51328
#define OFF_INV  (OFF_Q + 16*66)         // 52384
#define OFF_WMAX (OFF_INV + 16)          // 52400
#define SMEM_FLOATS (OFF_WMAX + 256)     // 52656 -> 210,624 B

__global__ __launch_bounds__(512, 1) void attn_kernel()
{
    extern __shared__ float smem[];
    float*    sc   = smem;
    uint32_t* sc_u = (uint32_t*)smem;
    uint32_t* ST   = (uint32_t*)(smem + OFF_ST);
    float*    Qs   = smem + OFF_Q;
    float*    inv  = smem + OFF_INV;
    float*    wmax = smem + OFF_WMAX;

    const int tid = threadIdx.x;
    const int w   = tid >> 5, lane = tid & 31;
    const int gid = lane >> 2, tig = lane & 3;
    const int bh  = blockIdx.y;
    const int t0  = blockIdx.x * TM;
    const int b   = bh >> 4, h = bh & 15;

    const float* Qg = g_Q + (size_t)bh * Sq * Dq;
    const uint4* Kb4[2] = { (const uint4*)(g_Kbh + ((size_t)bh << 16)),
                            (const uint4*)(g_Kbl + ((size_t)bh << 16)) };
    const uint4* Vb4[2] = { (const uint4*)(g_Vbh + ((size_t)bh << 16)),
                            (const uint4*)(g_Vbl + ((size_t)bh << 16)) };

    const uint32_t* Wbuf = ST + w * WSL;
    const uint32_t wb_b  = smem_u32(ST) + ((w * WSL) << 2);

    int sarr[4], srr[4], sq[4];
    #pragma unroll
    for (int k = 0; k < 4; ++k) {
        int idx = lane + k * 32;
        sarr[k] = idx >> 6;
        srr[k]  = (idx >> 3) & 7;
        sq[k]   = idx & 7;
    }
    const int nd = w & 7, kh = w >> 3;

    // ---- prefetch K chunk 0 ----
    #pragma unroll
    for (int k = 0; k < 4; ++k)
        cpa16(wb_b + ((sarr[k] * 288 + srr[k] * 36 + sq[k] * 4) << 2),
              Kb4[sarr[k]] + ((w * 8 + srr[k]) * 8 + sq[k]));
    CPA_COMMIT();

    // ---- Q stage ----
    for (int i = tid; i < TM * Dq; i += 512) {
        int r = i >> 6, d = i & 63;
        Qs[r * 66 + d] = Qg[(size_t)(t0 + r) * Dq + d];
    }
    __syncthreads();

    // ---- Q fragments ----
    uint32_t ahq[4][4], alq[4][4];
    #pragma unroll
    for (int ks = 0; ks < 4; ++ks) {
        float2 q[4];
        q[0] = *(float2*)&Qs[gid * 66 + ks * 16 + 2 * tig];
        q[1] = *(float2*)&Qs[(gid + 8) * 66 + ks * 16 + 2 * tig];
        q[2] = *(float2*)&Qs[gid * 66 + ks * 16 + 2 * tig + 8];
        q[3] = *(float2*)&Qs[(gid + 8) * 66 + ks * 16 + 2 * tig + 8];
        #pragma unroll
        for (int j = 0; j < 4; ++j) {
            uint32_t hh = bfpack(q[j].x, q[j].y);
            ahq[ks][j] = hh;
            alq[ks][j] = bfpack(q[j].x - bflowf(hh), q[j].y - bfhighf(hh));
        }
    }

    // ---- QK^T: 16 chunks of 128 s, warp-decoupled, track row max ----
    float mx0 = -3.402823466e+38f, mx1 = -3.402823466e+38f;

    for (int c = 0; c < 16; ++c) {
        const int buf = c & 1;
        if (c < 15) {
            const int bo2 = (buf ^ 1) * 576;
            #pragma unroll
            for (int k = 0; k < 4; ++k)
                cpa16(wb_b + ((bo2 + sarr[k] * 288 + srr[k] * 36 + sq[k] * 4) << 2),
                      Kb4[sarr[k]] + (((c + 1) * 128 + w * 8 + srr[k]) * 8 + sq[k]));
            CPA_COMMIT();
            CPA_WAIT1();
        } else {
            CPA_WAIT0();
        }
        __syncwarp();

        const uint32_t* KH = Wbuf + buf * 576;
        const uint32_t* KL = KH + 288;
        float cf[4] = {0.f, 0.f, 0.f, 0.f};
        #pragma unroll
        for (int ks = 0; ks < 4; ++ks) {
            uint32_t b0h = KH[gid * 36 + ks * 8 + tig];
            uint32_t b1h = KH[gid * 36 + ks * 8 + 4 + tig];
            uint32_t b0l = KL[gid * 36 + ks * 8 + tig];
            uint32_t b1l = KL[gid * 36 + ks * 8 + 4 + tig];
            mma_bf16(cf, ahq[ks], b0h, b1h);
            mma_bf16(cf, ahq[ks], b0l, b1l);
            mma_bf16(cf, alq[ks], b0h, b1h);
        }
        const int sg = (c << 7) + w * 8 + 2 * tig;
        float v0 = cf[0] * SCOREMUL; if (sg     == t0 + gid)     v0 *= DIAGMUL;
        float v1 = cf[1] * SCOREMUL; if (sg + 1 == t0 + gid)     v1 *= DIAGMUL;
        float v2 = cf[2] * SCOREMUL; if (sg     == t0 + gid + 8) v2 *= DIAGMUL;
        float v3 = cf[3] * SCOREMUL; if (sg + 1 == t0 + gid + 8) v3 *= DIAGMUL;
        mx0 = fmaxf(mx0, fmaxf(v0, v1));
        mx1 = fmaxf(mx1, fmaxf(v2, v3));
        *(float2*)&sc[gid * RS + sg]       = make_float2(v0, v1);
        *(float2*)&sc[(gid + 8) * RS + sg] = make_float2(v2, v3);
        __syncwarp();
    }
    mx0 = fmaxf(mx0, __shfl_xor_sync(0xFFFFFFFFu, mx0, 1));
    mx0 = fmaxf(mx0, __shfl_xor_sync(0xFFFFFFFFu, mx0, 2));
    mx1 = fmaxf(mx1, __shfl_xor_sync(0xFFFFFFFFu, mx1, 1));
    mx1 = fmaxf(mx1, __shfl_xor_sync(0xFFFFFFFFu, mx1, 2));
    if (tig == 0) {
        wmax[w * 16 + gid]     = mx0;
        wmax[w * 16 + gid + 8] = mx1;
    }
    __syncthreads();

    // ---- middle (one warp per row): radix top-k + fused boost/exp/pack ----
    {
        const int r = w;
        unsigned* hw   = (unsigned*)(ST + w * WSL);
        unsigned* cbuf = (unsigned*)(ST + w * WSL) + 256;

        float tmx = (lane < 16) ? wmax[lane * 16 + r] : -3.402823466e+38f;
        #pragma unroll
        for (int o = 8; o; o >>= 1) tmx = fmaxf(tmx, __shfl_xor_sync(0xFFFFFFFFu, tmx, o));
        tmx = __shfl_sync(0xFFFFFFFFu, tmx, 0);
        const float M = (tmx > 0.0f) ? tmx * MASKMUL : tmx;

        // ---- pass 1: full scan ----
        #pragma unroll
        for (int j = 0; j < 8; ++j) hw[lane + j * 32] = 0;
        __syncwarp();
        for (int j = 0; j < 16; ++j) {
            float4 v4 = *(const float4*)&sc[r * RS + ((j * 32 + lane) << 2)];
            atomicAdd(&hw[fmap(v4.x) >> 24], 1u);
            atomicAdd(&hw[fmap(v4.y) >> 24], 1u);
            atomicAdd(&hw[fmap(v4.z) >> 24], 1u);
            atomicAdd(&hw[fmap(v4.w) >> 24], 1u);
        }
        __syncwarp();
        int bsel, nk, bcnt;
        radix_pick(hw, lane, KKq, bsel, nk, bcnt);
        unsigned thrp = ((unsigned)bsel) << 24;
        int kneed = nk;
        __syncwarp();

        if (bcnt <= CCAP) {
            // ---- compact the selected top-byte bucket ----
            const unsigned pb = thrp >> 24;
            int nc = 0;
            for (int j = 0; j < 16; ++j) {
                float4 v4 = *(const float4*)&sc[r * RS + ((j * 32 + lane) << 2)];
                unsigned u[4] = { fmap(v4.x), fmap(v4.y), fmap(v4.z), fmap(v4.w) };
                #pragma unroll
                for (int e = 0; e < 4; ++e) {
                    bool ok = (u[e] >> 24) == pb;
                    unsigned bal = __ballot_sync(0xFFFFFFFFu, ok);
                    if (ok)
                        cbuf[nc + __popc(bal & ((1u << lane) - 1u))] = u[e];
                    nc += __popc(bal);
                }
            }
            __syncwarp();
            for (int shift = 16; shift >= 0; shift -= 8) {
                #pragma unroll
                for (int j = 0; j < 8; ++j) hw[lane + j * 32] = 0;
                __syncwarp();
                for (int i = lane; i < nc; i += 32) {
                    unsigned u = cbuf[i];
                    if (((u ^ thrp) >> (shift + 8)) == 0)
                        atomicAdd(&hw[(u >> shift) & 255], 1u);
                }
                __syncwarp();
                radix_pick(hw, lane, kneed, bsel, nk, bcnt);
                thrp |= ((unsigned)bsel) << shift;
                kneed = nk;
                __syncwarp();
            }
        } else {
            // ---- fallback: full scans ----
            for (int shift = 16; shift >= 0; shift -= 8) {
                #pragma unroll
                for (int j = 0; j < 8; ++j) hw[lane + j * 32] = 0;
                __syncwarp();
                for (int j = 0; j < 16; ++j) {
                    float4 v4 = *(const float4*)&sc[r * RS + ((j * 32 + lane) << 2)];
                    unsigned u0 = fmap(v4.x), u1 = fmap(v4.y);
                    unsigned u2 = fmap(v4.z), u3 = fmap(v4.w);
                    if (((u0 ^ thrp) >> (shift + 8)) == 0) atomicAdd(&hw[(u0 >> shift) & 255], 1u);
                    if (((u1 ^ thrp) >> (shift + 8)) == 0) atomicAdd(&hw[(u1 >> shift) & 255], 1u);
                    if (((u2 ^ thrp) >> (shift + 8)) == 0) atomicAdd(&hw[(u2 >> shift) & 255], 1u);
                    if (((u3 ^ thrp) >> (shift + 8)) == 0) atomicAdd(&hw[(u3 >> shift) & 255], 1u);
                }
                __syncwarp();
                radix_pick(hw, lane, kneed, bsel, nk, bcnt);
                thrp |= ((unsigned)bsel) << shift;
                kneed = nk;
                __syncwarp();
            }
        }

        // ---- fused: boost + exp + sum + bf16 hi/lo pack ----
        float sum = 0.0f;
        for (int j = 0; j < 16; ++j) {
            const int base = r * RS + ((j * 32 + lane) << 2);
            float4 v4 = *(const float4*)&sc[base];
            float x0 = (fmap(v4.x) >= thrp) ? v4.x * MASKMUL : v4.x;
            float x1 = (fmap(v4.y) >= thrp) ? v4.y * MASKMUL : v4.y;
            float x2 = (fmap(v4.z) >= thrp) ? v4.z * MASKMUL : v4.z;
            float x3 = (fmap(v4.w) >= thrp) ? v4.w * MASKMUL : v4.w;
            float e0 = __expf(x0 - M);
            float e1 = __expf(x1 - M);
            float e2 = __expf(x2 - M);
            float e3 = __expf(x3 - M);
            sum += (e0 + e1) + (e2 + e3);
            uint32_t h0 = bfpack(e0, e1);
            uint32_t l0 = bfpack(e0 - bflowf(h0), e1 - bfhighf(h0));
            uint32_t h1 = bfpack(e2, e3);
            uint32_t l1 = bfpack(e2 - bflowf(h1), e3 - bfhighf(h1));
            uint4 pk; pk.x = h0; pk.y = l0; pk.z = h1; pk.w = l1;
            *(uint4*)&sc_u[base] = pk;
        }
        #pragma unroll
        for (int o = 16; o; o >>= 1) sum += __shfl_xor_sync(0xFFFFFFFFu, sum, o);
        if (lane == 0) inv[r] = 1.0f / sum;
    }

    // prefetch V chunk 0 into own slice
    #pragma unroll
    for (int k = 0; k < 4; ++k)
        cpa16(wb_b + ((sarr[k] * 288 + srr[k] * 36 + sq[k] * 4) << 2),
              Vb4[sarr[k]] + ((nd * 8 + srr[k]) * 256 + kh * 8 + sq[k]));
    CPA_COMMIT();
    __syncthreads();

    // ---- P @ V: 16 chunks of 128 s, warp-decoupled ----
    float cacc[4] = {0.f, 0.f, 0.f, 0.f};

    for (int c = 0; c < 16; ++c) {
        const int buf = c & 1;
        if (c < 15) {
            const int bo2 = (buf ^ 1) * 576;
            #pragma unroll
            for (int k = 0; k < 4; ++k)
                cpa16(wb_b + ((bo2 + sarr[k] * 288 + srr[k] * 36 + sq[k] * 4) << 2),
                      Vb4[sarr[k]] + ((nd * 8 + srr[k]) * 256 + (c + 1) * 16 + kh * 8 + sq[k]));
            CPA_COMMIT();
            CPA_WAIT1();
        } else {
            CPA_WAIT0();
        }
        __syncwarp();

        const uint32_t* VH = Wbuf + buf * 576;
        const uint32_t* VL = VH + 288;

        #pragma unroll
        for (int kk = 0; kk < 4; ++kk) {
            const int kp = kh * 4 + kk;
            const int k0 = (c << 7) + (kp << 4);
            uint2 A0 = *(uint2*)&sc_u[gid * RS + k0 + 2 * tig];
            uint2 A1 = *(uint2*)&sc_u[(gid + 8) * RS + k0 + 2 * tig];
            uint2 A2 = *(uint2*)&sc_u[gid * RS + k0 + 8 + 2 * tig];
            uint2 A3 = *(uint2*)&sc_u[(gid + 8) * RS + k0 + 8 + 2 * tig];
            uint32_t ah[4] = {A0.x, A1.x, A2.x, A3.x};
            uint32_t al[4] = {A0.y, A1.y, A2.y, A3.y};

            uint32_t b0h = VH[gid * 36 + kk * 8 + tig];
            uint32_t b1h = VH[gid * 36 + kk * 8 + 4 + tig];
            uint32_t b0l = VL[gid * 36 + kk * 8 + tig];
            uint32_t b1l = VL[gid * 36 + kk * 8 + 4 + tig];
            mma_bf16(cacc, ah, b0h, b1h);
            mma_bf16(cacc, ah, b0l, b1l);
            mma_bf16(cacc, al, b0h, b1h);
        }
        __syncwarp();
    }

    // ---- partials into own slice, reduce across kh, write g_O ----
    {
        float* PS = (float*)(ST + w * WSL);
        PS[gid * 8 + 2 * tig]           = cacc[0];
        PS[gid * 8 + 2 * tig + 1]       = cacc[1];
        PS[(gid + 8) * 8 + 2 * tig]     = cacc[2];
        PS[(gid + 8) * 8 + 2 * tig + 1] = cacc[3];
    }
    __syncthreads();

    {
        const float* PSb = (const float*)ST;
        for (int i = tid; i < TM * Dq; i += 512) {
            int r = i >> 6, d = i & 63;
            int n2 = d >> 3, dd = d & 7;
            float o = (PSb[(size_t)n2 * WSL + r * 8 + dd] +
                       PSb[(size_t)(8 + n2) * WSL + r * 8 + dd]) * inv[r];
            g_O[((size_t)(b * Sq + t0 + r)) * Eq + h * Dq + d] = o;
        }
    }
}

// ---------------------------------------------------------------------------
// Launch
// ---------------------------------------------------------------------------
extern "C" void kernel_launch(void* const* d_in, const int* in_sizes, int n_in,
                              void* d_out, int out_size)
{
    const float* query = (const float*)d_in[0];
    const float* key   = (const float*)d_in[1];
    const float* value = (const float*)d_in[2];
    const float* Wq    = (const float*)d_in[3];
    const float* bq    = (const float*)d_in[4];
    const float* Wk    = (const float*)d_in[5];
    const float* bk    = (const float*)d_in[6];
    const float* Wv    = (const float*)d_in[7];
    const float* bv    = (const float*)d_in[8];
    const float* Wo    = (const float*)d_in[9];
    const float* bo    = (const float*)d_in[10];
    const float* ts    = (const float*)d_in[11];

    cudaFuncSetAttribute(attn_kernel, cudaFuncAttributeMaxDynamicSharedMemorySize,
                         SMEM_FLOATS * 4);

    dim3 gT(Eq / 32, Eq / 32, 4);
    wtrans_kernel<<<gT, dim3(32, 8)>>>(Wq, Wk, Wv, Wo);

    float* wt; cudaGetSymbolAddress((void**)&wt, g_Wt);

    dim3 gQKV(Eq / 128, (Bq * Sq) / 128, 3);
    gemm_qkv_kernel<<<gQKV, 256>>>(query, key, value, wt, bq, bk, bv, ts);

    conv_v_kernel<<<8192, 256>>>();

    dim3 gAttn(Sq / TM, Bq * Hq);
    attn_kernel<<<gAttn, 512, SMEM_FLOATS * 4>>>();

    dim3 gO(Eq / 128, (Bq * Sq) / 128);
    gemm_out_kernel<<<gO, 256>>>(wt, bo, (float*)d_out);
}

// round 17
// speedup vs baseline: 1.1359x; 1.0053x over previous
#include <cuda_runtime.h>
#include <cstdint>

// Problem constants
#define Bq 2
#define Sq 2048
#define Eq 1024
#define Hq 16
#define Dq 64
#define KKq 409           // max(1, int(S*0.2))
#define SCOREMUL 0.15625f // (1/sqrt(64)) / temperature, temperature = 0.8
#define DIAGMUL  1.15f    // 1 + ACH*0.3
#define MASKMUL  1.15f    // 1 + (-DA)*0.3

#define TM 16             // query rows per attention block
#define RS 2056           // sc row stride (floats); 2056 % 32 == 8 -> conflict-free
#define WSL 1152          // u32 per warp staging slice
#define CCAP 896          // compaction buffer capacity (WSL - 256 hist bins)

// ---------------------------------------------------------------------------
// Scratch (device globals)
// ---------------------------------------------------------------------------
__device__ float    g_Q [Bq*Hq*Sq*Dq];   // (b,h,s,d)
__device__ float    g_V [Bq*Hq*Sq*Dq];   // (b,h,s,d)
__device__ float    g_O [Bq*Sq*Eq];      // (b,s,e)
__device__ float    g_Wt[4*Eq*Eq];       // Wq^T, Wk^T, Wv^T, Wo^T
__device__ uint32_t g_Kbh[Bq*Hq*Sq*32];  // K bf16 hi, (bh, s, d2)
__device__ uint32_t g_Kbl[Bq*Hq*Sq*32];  // K bf16 lo
__device__ uint32_t g_Vbh[Bq*Hq*Dq*1024];// V bf16 hi, (bh, d, s2)
__device__ uint32_t g_Vbl[Bq*Hq*Dq*1024];// V bf16 lo

// ---------------------------------------------------------------------------
// helpers
// ---------------------------------------------------------------------------
__device__ __forceinline__ uint32_t bfpack(float lo, float hi) {
    uint32_t r;
    asm("cvt.rn.bf16x2.f32 %0, %1, %2;" : "=r"(r) : "f"(hi), "f"(lo));
    return r;
}
__device__ __forceinline__ float bflowf(uint32_t p)  { return __uint_as_float(p << 16); }
__device__ __forceinline__ float bfhighf(uint32_t p) { return __uint_as_float(p & 0xFFFF0000u); }

__device__ __forceinline__ void mma_bf16(float* d, const uint32_t* a, uint32_t b0, uint32_t b1) {
    asm volatile(
        "mma.sync.aligned.m16n8k16.row.col.f32.bf16.bf16.f32 "
        "{%0,%1,%2,%3}, {%4,%5,%6,%7}, {%8,%9}, {%0,%1,%2,%3};"
        : "+f"(d[0]), "+f"(d[1]), "+f"(d[2]), "+f"(d[3])
        : "r"(a[0]), "r"(a[1]), "r"(a[2]), "r"(a[3]), "r"(b0), "r"(b1));
}

__device__ __forceinline__ unsigned fmap(float f) {
    unsigned u = __float_as_uint(f);
    return (u & 0x80000000u) ? ~u : (u | 0x80000000u);
}

__device__ __forceinline__ uint32_t smem_u32(const void* p) {
    uint32_t a;
    asm("{ .reg .u64 t; cvta.to.shared.u64 t, %1; cvt.u32.u64 %0, t; }" : "=r"(a) : "l"(p));
    return a;
}
__device__ __forceinline__ void cpa16(uint32_t dst, const void* src) {
    asm volatile("cp.async.cg.shared.global [%0], [%1], 16;" :: "r"(dst), "l"(src) : "memory");
}
#define CPA_COMMIT() asm volatile("cp.async.commit_group;" ::: "memory")
#define CPA_WAIT1()  asm volatile("cp.async.wait_group 1;" ::: "memory")
#define CPA_WAIT0()  asm volatile("cp.async.wait_group 0;" ::: "memory")

// warp radix-select step
__device__ __forceinline__ void radix_pick(const unsigned* hw, int lane, int kneed,
                                           int& bsel, int& nk, int& bcnt) {
    const int b0 = (31 - lane) * 8;
    unsigned cb[8], cl = 0;
    #pragma unroll
    for (int j = 0; j < 8; ++j) { cb[j] = hw[b0 + j]; cl += cb[j]; }
    unsigned S = cl;
    #pragma unroll
    for (int o = 1; o < 32; o <<= 1) {
        unsigned x = __shfl_up_sync(0xFFFFFFFFu, S, o);
        if (lane >= o) S += x;
    }
    unsigned excl = S - cl;
    bool has = (excl < (unsigned)kneed) && ((unsigned)kneed <= S);
    unsigned bal = __ballot_sync(0xFFFFFFFFu, has);
    int src = __ffs(bal) - 1;
    int bs = 0, n = 0, c = 0;
    if (lane == src) {
        int rem = kneed - (int)excl;
        #pragma unroll
        for (int j = 7; j >= 0; --j) {
            int cnt = (int)cb[j];
            if (rem <= cnt) { bs = b0 + j; n = rem; c = cnt; break; }
            rem -= cnt;
        }
    }
    bsel = __shfl_sync(0xFFFFFFFFu, bs, src);
    nk   = __shfl_sync(0xFFFFFFFFu, n, src);
    bcnt = __shfl_sync(0xFFFFFFFFu, c, src);
}

// ---------------------------------------------------------------------------
// Weight transpose: g_Wt[z] = W(z)^T
// ---------------------------------------------------------------------------
__global__ void wtrans_kernel(const float* __restrict__ Wq, const float* __restrict__ Wk,
                              const float* __restrict__ Wv, const float* __restrict__ Wo)
{
    __shared__ float t[32][33];
    const int z = blockIdx.z;
    const float* W = (z == 0) ? Wq : (z == 1) ? Wk : (z == 2) ? Wv : Wo;
    float* out = g_Wt + (size_t)z * Eq * Eq;
    const int x0 = blockIdx.x * 32, y0 = blockIdx.y * 32;
    const int tx = threadIdx.x, ty = threadIdx.y;
    #pragma unroll
    for (int i = 0; i < 32; i += 8)
        t[ty + i][tx] = W[(size_t)(y0 + ty + i) * Eq + x0 + tx];
    __syncthreads();
    #pragma unroll
    for (int i = 0; i < 32; i += 8)
        out[(size_t)(x0 + ty + i) * Eq + y0 + tx] = t[tx][ty + i];
}

// ---------------------------------------------------------------------------
// Convert V fp32 -> bf16 hi/lo (bh, d, s2)
// ---------------------------------------------------------------------------
__global__ __launch_bounds__(256) void conv_v_kernel()
{
    const int i = blockIdx.x * 256 + threadIdx.x;
    const int bh = i >> 16, rem = i & 65535;
    const int d = rem >> 10, s2 = rem & 1023;
    float v0 = g_V[(((size_t)(bh << 11) + 2 * s2)     << 6) + d];
    float v1 = g_V[(((size_t)(bh << 11) + 2 * s2 + 1) << 6) + d];
    uint32_t hh = bfpack(v0, v1);
    g_Vbh[i] = hh;
    g_Vbl[i] = bfpack(v0 - bflowf(hh), v1 - bfhighf(hh));
}

// ---------------------------------------------------------------------------
// bf16x3 mma GEMM core (validated)
// ---------------------------------------------------------------------------
#define SROW 20

__device__ __forceinline__ void gemm_core(
    const float* __restrict__ A, const float* __restrict__ Bt,
    uint32_t* Ahi, uint32_t* Alo, uint32_t* Bhi, uint32_t* Blo,
    int m0, int n0, float acc[2][8][4])
{
    const int tid  = threadIdx.x;
    const int wid  = tid >> 5, lane = tid & 31;
    const int gid  = lane >> 2, tig = lane & 3;
    const int wm   = wid & 3,  wn  = wid >> 2;

    const float4* pa[4];
    const float4* pb[4];
    int so[4];
    #pragma unroll
    for (int j = 0; j < 4; ++j) {
        int f4  = tid + j * 256;
        int row = f4 >> 3;
        int cq  = f4 & 7;
        pa[j] = (const float4*)(A  + (size_t)(m0 + row) * Eq) + cq;
        pb[j] = (const float4*)(Bt + (size_t)(n0 + row) * Eq) + cq;
        so[j] = row * SROW + cq * 2;
    }

    float4 ra[4], rb[4];
    #pragma unroll
    for (int j = 0; j < 4; ++j) { ra[j] = pa[j][0]; rb[j] = pb[j][0]; }

    for (int kc = 0; kc < 32; ++kc) {
        __syncthreads();
        #pragma unroll
        for (int j = 0; j < 4; ++j) {
            uint32_t h0 = bfpack(ra[j].x, ra[j].y);
            uint32_t h1 = bfpack(ra[j].z, ra[j].w);
            Ahi[so[j]]     = h0;
            Ahi[so[j] + 1] = h1;
            Alo[so[j]]     = bfpack(ra[j].x - bflowf(h0), ra[j].y - bfhighf(h0));
            Alo[so[j] + 1] = bfpack(ra[j].z - bflowf(h1), ra[j].w - bfhighf(h1));
            uint32_t g0 = bfpack(rb[j].x, rb[j].y);
            uint32_t g1 = bfpack(rb[j].z, rb[j].w);
            Bhi[so[j]]     = g0;
            Bhi[so[j] + 1] = g1;
            Blo[so[j]]     = bfpack(rb[j].x - bflowf(g0), rb[j].y - bfhighf(g0));
            Blo[so[j] + 1] = bfpack(rb[j].z - bflowf(g1), rb[j].w - bfhighf(g1));
        }
        __syncthreads();

        if (kc < 31) {
            #pragma unroll
            for (int j = 0; j < 4; ++j) {
                ra[j] = pa[j][(kc + 1) * 8];
                rb[j] = pb[j][(kc + 1) * 8];
            }
        }

        #pragma unroll
        for (int ks = 0; ks < 2; ++ks) {
            const int kb = ks * 8;
            uint32_t ah[2][4], al[2][4];
            #pragma unroll
            for (int mt = 0; mt < 2; ++mt) {
                const int r0 = wm * 32 + mt * 16 + gid;
                ah[mt][0] = Ahi[r0 * SROW + kb + tig];
                ah[mt][1] = Ahi[(r0 + 8) * SROW + kb + tig];
                ah[mt][2] = Ahi[r0 * SROW + kb + tig + 4];
                ah[mt][3] = Ahi[(r0 + 8) * SROW + kb + tig + 4];
                al[mt][0] = Alo[r0 * SROW + kb + tig];
                al[mt][1] = Alo[(r0 + 8) * SROW + kb + tig];
                al[mt][2] = Alo[r0 * SROW + kb + tig + 4];
                al[mt][3] = Alo[(r0 + 8) * SROW + kb + tig + 4];
            }
            #pragma unroll
            for (int nt = 0; nt < 8; ++nt) {
                const int n = wn * 64 + nt * 8 + gid;
                uint32_t bh0 = Bhi[n * SROW + kb + tig];
                uint32_t bh1 = Bhi[n * SROW + kb + tig + 4];
                uint32_t bl0 = Blo[n * SROW + kb + tig];
                uint32_t bl1 = Blo[n * SROW + kb + tig + 4];
                #pragma unroll
                for (int mt = 0; mt < 2; ++mt) {
                    mma_bf16(acc[mt][nt], ah[mt], bh0, bh1);
                    mma_bf16(acc[mt][nt], ah[mt], bl0, bl1);
                    mma_bf16(acc[mt][nt], al[mt], bh0, bh1);
                }
            }
        }
    }
}

// ---------------------------------------------------------------------------
// Fused QKV GEMM:
//   mode 0: query@Wq -> g_Q (b,h,s,d) +bq
//   mode 1: key@Wk   -> g_Kbh/l bf16 (bh,s,d2), (+bk)*ts[h]
//   mode 2: value@Wv -> g_V (b,h,s,d) +bv
// ---------------------------------------------------------------------------
__global__ __launch_bounds__(256, 2) void gemm_qkv_kernel(
    const float* __restrict__ query, const float* __restrict__ key,
    const float* __restrict__ value, const float* __restrict__ wt,
    const float* __restrict__ bq, const float* __restrict__ bk,
    const float* __restrict__ bv, const float* __restrict__ ts)
{
    __shared__ uint32_t sb[4 * 128 * SROW];
    const int mode = blockIdx.z;
    const float* A    = (mode == 0) ? query : (mode == 1) ? key : value;
    const float* Bt   = wt + (size_t)mode * Eq * Eq;
    const float* bias = (mode == 0) ? bq : (mode == 1) ? bk : bv;

    const int tid = threadIdx.x;
    const int wid = tid >> 5, lane = tid & 31;
    const int gid = lane >> 2, tig = lane & 3;
    const int wm  = wid & 3,  wn  = wid >> 2;
    const int m0  = blockIdx.y * 128, n0 = blockIdx.x * 128;

    float acc[2][8][4];
    #pragma unroll
    for (int mt = 0; mt < 2; ++mt)
        #pragma unroll
        for (int nt = 0; nt < 8; ++nt)
            #pragma unroll
            for (int c = 0; c < 4; ++c) acc[mt][nt][c] = 0.0f;

    gemm_core(A, Bt, sb, sb + 128 * SROW, sb + 2 * 128 * SROW, sb + 3 * 128 * SROW,
              m0, n0, acc);

    #pragma unroll
    for (int mt = 0; mt < 2; ++mt) {
        const int row = m0 + wm * 32 + mt * 16 + gid;
        const int bb = row >> 11, s = row & (Sq - 1);
        #pragma unroll
        for (int nt = 0; nt < 8; ++nt) {
            const int col = n0 + wn * 64 + nt * 8 + 2 * tig;
            const int h = col >> 6, dd = col & 63;
            const float* d = acc[mt][nt];
            float2 bvv = *(const float2*)(bias + col);
            if (mode == 1) {
                const float tv = ts[h];
                float v0 = (d[0] + bvv.x) * tv, v1 = (d[1] + bvv.y) * tv;
                float v2 = (d[2] + bvv.x) * tv, v3 = (d[3] + bvv.y) * tv;
                size_t idx = ((size_t)(bb * Hq + h) << 16) + s * 32 + (dd >> 1);
                uint32_t h0 = bfpack(v0, v1);
                g_Kbh[idx] = h0;
                g_Kbl[idx] = bfpack(v0 - bflowf(h0), v1 - bfhighf(h0));
                uint32_t h1 = bfpack(v2, v3);
                g_Kbh[idx + 256] = h1;
                g_Kbl[idx + 256] = bfpack(v2 - bflowf(h1), v3 - bfhighf(h1));
            } else {
                float* base = (mode == 0) ? g_Q : g_V;
                float* dst = base + ((size_t)(bb * Hq + h) * Sq + s) * Dq + dd;
                *(float2*)(dst)          = make_float2(d[0] + bvv.x, d[1] + bvv.y);
                *(float2*)(dst + 8 * Dq) = make_float2(d[2] + bvv.x, d[3] + bvv.y);
            }
        }
    }
}

// ---------------------------------------------------------------------------
// Output GEMM: d_out = g_O @ Wo + bo
// ---------------------------------------------------------------------------
__global__ __launch_bounds__(256, 2) void gemm_out_kernel(
    const float* __restrict__ wt, const float* __restrict__ bo,
    float* __restrict__ Cout)
{
    __shared__ uint32_t sb[4 * 128 * SROW];
    const int tid = threadIdx.x;
    const int wid = tid >> 5, lane = tid & 31;
    const int gid = lane >> 2, tig = lane & 3;
    const int wm  = wid & 3,  wn  = wid >> 2;
    const int m0  = blockIdx.y * 128, n0 = blockIdx.x * 128;

    float acc[2][8][4];
    #pragma unroll
    for (int mt = 0; mt < 2; ++mt)
        #pragma unroll
        for (int nt = 0; nt < 8; ++nt)
            #pragma unroll
            for (int c = 0; c < 4; ++c) acc[mt][nt][c] = 0.0f;

    gemm_core(g_O, wt + 3 * (size_t)Eq * Eq,
              sb, sb + 128 * SROW, sb + 2 * 128 * SROW, sb + 3 * 128 * SROW,
              m0, n0, acc);

    #pragma unroll
    for (int mt = 0; mt < 2; ++mt) {
        const int row = m0 + wm * 32 + mt * 16 + gid;
        #pragma unroll
        for (int nt = 0; nt < 8; ++nt) {
            const int col = n0 + wn * 64 + nt * 8 + 2 * tig;
            const float* d = acc[mt][nt];
            float2 bvv = *(const float2*)(bo + col);
            *(float2*)(Cout + (size_t)row * Eq + col) =
                make_float2(d[0] + bvv.x, d[1] + bvv.y);
            *(float2*)(Cout + (size_t)(row + 8) * Eq + col) =
                make_float2(d[2] + bvv.x, d[3] + bvv.y);
        }
    }
}

// ---------------------------------------------------------------------------
// Fused attention (R16 pipeline, RS=2056) + dual accumulators in QK/PV
// (isolated retest of the R13 chain-split without match_any).
// ---------------------------------------------------------------------------
#define OFF_ST   (TM * RS)               // 32896
#define OFF_Q    (OFF_ST + 18432)        // 51328
#define OFF_INV  (OFF_Q + 16*66)         // 52384
#define OFF_WMAX (OFF_INV + 16)          // 52400
#define SMEM_FLOATS (OFF_WMAX + 256)     // 52656 -> 210,624 B

__global__ __launch_bounds__(512, 1) void attn_kernel()
{
    extern __shared__ float smem[];
    float*    sc   = smem;
    uint32_t* sc_u = (uint32_t*)smem;
    uint32_t* ST   = (uint32_t*)(smem + OFF_ST);
    float*    Qs   = smem + OFF_Q;
    float*    inv  = smem + OFF_INV;
    float*    wmax = smem + OFF_WMAX;

    const int tid = threadIdx.x;
    const int w   = tid >> 5, lane = tid & 31;
    const int gid = lane >> 2, tig = lane & 3;
    const int bh  = blockIdx.y;
    const int t0  = blockIdx.x * TM;
    const int b   = bh >> 4, h = bh & 15;

    const float* Qg = g_Q + (size_t)bh * Sq * Dq;
    const uint4* Kb4[2] = { (const uint4*)(g_Kbh + ((size_t)bh << 16)),
                            (const uint4*)(g_Kbl + ((size_t)bh << 16)) };
    const uint4* Vb4[2] = { (const uint4*)(g_Vbh + ((size_t)bh << 16)),
                            (const uint4*)(g_Vbl + ((size_t)bh << 16)) };

    const uint32_t* Wbuf = ST + w * WSL;
    const uint32_t wb_b  = smem_u32(ST) + ((w * WSL) << 2);

    int sarr[4], srr[4], sq[4];
    #pragma unroll
    for (int k = 0; k < 4; ++k) {
        int idx = lane + k * 32;
        sarr[k] = idx >> 6;
        srr[k]  = (idx >> 3) & 7;
        sq[k]   = idx & 7;
    }
    const int nd = w & 7, kh = w >> 3;

    // ---- prefetch K chunk 0 ----
    #pragma unroll
    for (int k = 0; k < 4; ++k)
        cpa16(wb_b + ((sarr[k] * 288 + srr[k] * 36 + sq[k] * 4) << 2),
              Kb4[sarr[k]] + ((w * 8 + srr[k]) * 8 + sq[k]));
    CPA_COMMIT();

    // ---- Q stage ----
    for (int i = tid; i < TM * Dq; i += 512) {
        int r = i >> 6, d = i & 63;
        Qs[r * 66 + d] = Qg[(size_t)(t0 + r) * Dq + d];
    }
    __syncthreads();

    // ---- Q fragments ----
    uint32_t ahq[4][4], alq[4][4];
    #pragma unroll
    for (int ks = 0; ks < 4; ++ks) {
        float2 q[4];
        q[0] = *(float2*)&Qs[gid * 66 + ks * 16 + 2 * tig];
        q[1] = *(float2*)&Qs[(gid + 8) * 66 + ks * 16 + 2 * tig];
        q[2] = *(float2*)&Qs[gid * 66 + ks * 16 + 2 * tig + 8];
        q[3] = *(float2*)&Qs[(gid + 8) * 66 + ks * 16 + 2 * tig + 8];
        #pragma unroll
        for (int j = 0; j < 4; ++j) {
            uint32_t hh = bfpack(q[j].x, q[j].y);
            ahq[ks][j] = hh;
            alq[ks][j] = bfpack(q[j].x - bflowf(hh), q[j].y - bfhighf(hh));
        }
    }

    // ---- QK^T: 16 chunks of 128 s, dual accumulators (ks parity) ----
    float mx0 = -3.402823466e+38f, mx1 = -3.402823466e+38f;

    for (int c = 0; c < 16; ++c) {
        const int buf = c & 1;
        if (c < 15) {
            const int bo2 = (buf ^ 1) * 576;
            #pragma unroll
            for (int k = 0; k < 4; ++k)
                cpa16(wb_b + ((bo2 + sarr[k] * 288 + srr[k] * 36 + sq[k] * 4) << 2),
                      Kb4[sarr[k]] + (((c + 1) * 128 + w * 8 + srr[k]) * 8 + sq[k]));
            CPA_COMMIT();
            CPA_WAIT1();
        } else {
            CPA_WAIT0();
        }
        __syncwarp();

        const uint32_t* KH = Wbuf + buf * 576;
        const uint32_t* KL = KH + 288;
        float cfA[4] = {0.f, 0.f, 0.f, 0.f};
        float cfB[4] = {0.f, 0.f, 0.f, 0.f};
        #pragma unroll
        for (int ks = 0; ks < 4; ++ks) {
            float* cf = (ks & 1) ? cfB : cfA;
            uint32_t b0h = KH[gid * 36 + ks * 8 + tig];
            uint32_t b1h = KH[gid * 36 + ks * 8 + 4 + tig];
            uint32_t b0l = KL[gid * 36 + ks * 8 + tig];
            uint32_t b1l = KL[gid * 36 + ks * 8 + 4 + tig];
            mma_bf16(cf, ahq[ks], b0h, b1h);
            mma_bf16(cf, ahq[ks], b0l, b1l);
            mma_bf16(cf, alq[ks], b0h, b1h);
        }
        const int sg = (c << 7) + w * 8 + 2 * tig;
        float v0 = (cfA[0] + cfB[0]) * SCOREMUL; if (sg     == t0 + gid)     v0 *= DIAGMUL;
        float v1 = (cfA[1] + cfB[1]) * SCOREMUL; if (sg + 1 == t0 + gid)     v1 *= DIAGMUL;
        float v2 = (cfA[2] + cfB[2]) * SCOREMUL; if (sg     == t0 + gid + 8) v2 *= DIAGMUL;
        float v3 = (cfA[3] + cfB[3]) * SCOREMUL; if (sg + 1 == t0 + gid + 8) v3 *= DIAGMUL;
        mx0 = fmaxf(mx0, fmaxf(v0, v1));
        mx1 = fmaxf(mx1, fmaxf(v2, v3));
        *(float2*)&sc[gid * RS + sg]       = make_float2(v0, v1);
        *(float2*)&sc[(gid + 8) * RS + sg] = make_float2(v2, v3);
        __syncwarp();
    }
    mx0 = fmaxf(mx0, __shfl_xor_sync(0xFFFFFFFFu, mx0, 1));
    mx0 = fmaxf(mx0, __shfl_xor_sync(0xFFFFFFFFu, mx0, 2));
    mx1 = fmaxf(mx1, __shfl_xor_sync(0xFFFFFFFFu, mx1, 1));
    mx1 = fmaxf(mx1, __shfl_xor_sync(0xFFFFFFFFu, mx1, 2));
    if (tig == 0) {
        wmax[w * 16 + gid]     = mx0;
        wmax[w * 16 + gid + 8] = mx1;
    }
    __syncthreads();

    // ---- middle (one warp per row): radix top-k + fused boost/exp/pack ----
    {
        const int r = w;
        unsigned* hw   = (unsigned*)(ST + w * WSL);
        unsigned* cbuf = (unsigned*)(ST + w * WSL) + 256;

        float tmx = (lane < 16) ? wmax[lane * 16 + r] : -3.402823466e+38f;
        #pragma unroll
        for (int o = 8; o; o >>= 1) tmx = fmaxf(tmx, __shfl_xor_sync(0xFFFFFFFFu, tmx, o));
        tmx = __shfl_sync(0xFFFFFFFFu, tmx, 0);
        const float M = (tmx > 0.0f) ? tmx * MASKMUL : tmx;

        // ---- pass 1: full scan ----
        #pragma unroll
        for (int j = 0; j < 8; ++j) hw[lane + j * 32] = 0;
        __syncwarp();
        for (int j = 0; j < 16; ++j) {
            float4 v4 = *(const float4*)&sc[r * RS + ((j * 32 + lane) << 2)];
            atomicAdd(&hw[fmap(v4.x) >> 24], 1u);
            atomicAdd(&hw[fmap(v4.y) >> 24], 1u);
            atomicAdd(&hw[fmap(v4.z) >> 24], 1u);
            atomicAdd(&hw[fmap(v4.w) >> 24], 1u);
        }
        __syncwarp();
        int bsel, nk, bcnt;
        radix_pick(hw, lane, KKq, bsel, nk, bcnt);
        unsigned thrp = ((unsigned)bsel) << 24;
        int kneed = nk;
        __syncwarp();

        if (bcnt <= CCAP) {
            const unsigned pb = thrp >> 24;
            int nc = 0;
            for (int j = 0; j < 16; ++j) {
                float4 v4 = *(const float4*)&sc[r * RS + ((j * 32 + lane) << 2)];
                unsigned u[4] = { fmap(v4.x), fmap(v4.y), fmap(v4.z), fmap(v4.w) };
                #pragma unroll
                for (int e = 0; e < 4; ++e) {
                    bool ok = (u[e] >> 24) == pb;
                    unsigned bal = __ballot_sync(0xFFFFFFFFu, ok);
                    if (ok)
                        cbuf[nc + __popc(bal & ((1u << lane) - 1u))] = u[e];
                    nc += __popc(bal);
                }
            }
            __syncwarp();
            for (int shift = 16; shift >= 0; shift -= 8) {
                #pragma unroll
                for (int j = 0; j < 8; ++j) hw[lane + j * 32] = 0;
                __syncwarp();
                for (int i = lane; i < nc; i += 32) {
                    unsigned u = cbuf[i];
                    if (((u ^ thrp) >> (shift + 8)) == 0)
                        atomicAdd(&hw[(u >> shift) & 255], 1u);
                }
                __syncwarp();
                radix_pick(hw, lane, kneed, bsel, nk, bcnt);
                thrp |= ((unsigned)bsel) << shift;
                kneed = nk;
                __syncwarp();
            }
        } else {
            for (int shift = 16; shift >= 0; shift -= 8) {
                #pragma unroll
                for (int j = 0; j < 8; ++j) hw[lane + j * 32] = 0;
                __syncwarp();
                for (int j = 0; j < 16; ++j) {
                    float4 v4 = *(const float4*)&sc[r * RS + ((j * 32 + lane) << 2)];
                    unsigned u0 = fmap(v4.x), u1 = fmap(v4.y);
                    unsigned u2 = fmap(v4.z), u3 = fmap(v4.w);
                    if (((u0 ^ thrp) >> (shift + 8)) == 0) atomicAdd(&hw[(u0 >> shift) & 255], 1u);
                    if (((u1 ^ thrp) >> (shift + 8)) == 0) atomicAdd(&hw[(u1 >> shift) & 255], 1u);
                    if (((u2 ^ thrp) >> (shift + 8)) == 0) atomicAdd(&hw[(u2 >> shift) & 255], 1u);
                    if (((u3 ^ thrp) >> (shift + 8)) == 0) atomicAdd(&hw[(u3 >> shift) & 255], 1u);
                }
                __syncwarp();
                radix_pick(hw, lane, kneed, bsel, nk, bcnt);
                thrp |= ((unsigned)bsel) << shift;
                kneed = nk;
                __syncwarp();
            }
        }

        // ---- fused: boost + exp + sum + bf16 hi/lo pack ----
        float sum = 0.0f;
        for (int j = 0; j < 16; ++j) {
            const int base = r * RS + ((j * 32 + lane) << 2);
            float4 v4 = *(const float4*)&sc[base];
            float x0 = (fmap(v4.x) >= thrp) ? v4.x * MASKMUL : v4.x;
            float x1 = (fmap(v4.y) >= thrp) ? v4.y * MASKMUL : v4.y;
            float x2 = (fmap(v4.z) >= thrp) ? v4.z * MASKMUL : v4.z;
            float x3 = (fmap(v4.w) >= thrp) ? v4.w * MASKMUL : v4.w;
            float e0 = __expf(x0 - M);
            float e1 = __expf(x1 - M);
            float e2 = __expf(x2 - M);
            float e3 = __expf(x3 - M);
            sum += (e0 + e1) + (e2 + e3);
            uint32_t h0 = bfpack(e0, e1);
            uint32_t l0 = bfpack(e0 - bflowf(h0), e1 - bfhighf(h0));
            uint32_t h1 = bfpack(e2, e3);
            uint32_t l1 = bfpack(e2 - bflowf(h1), e3 - bfhighf(h1));
            uint4 pk; pk.x = h0; pk.y = l0; pk.z = h1; pk.w = l1;
            *(uint4*)&sc_u[base] = pk;
        }
        #pragma unroll
        for (int o = 16; o; o >>= 1) sum += __shfl_xor_sync(0xFFFFFFFFu, sum, o);
        if (lane == 0) inv[r] = 1.0f / sum;
    }

    // prefetch V chunk 0 into own slice
    #pragma unroll
    for (int k = 0; k < 4; ++k)
        cpa16(wb_b + ((sarr[k] * 288 + srr[k] * 36 + sq[k] * 4) << 2),
              Vb4[sarr[k]] + ((nd * 8 + srr[k]) * 256 + kh * 8 + sq[k]));
    CPA_COMMIT();
    __syncthreads();

    // ---- P @ V: 16 chunks of 128 s, dual accumulators (kk parity) ----
    float cacc0[4] = {0.f, 0.f, 0.f, 0.f};
    float cacc1[4] = {0.f, 0.f, 0.f, 0.f};

    for (int c = 0; c < 16; ++c) {
        const int buf = c & 1;
        if (c < 15) {
            const int bo2 = (buf ^ 1) * 576;
            #pragma unroll
            for (int k = 0; k < 4; ++k)
                cpa16(wb_b + ((bo2 + sarr[k] * 288 + srr[k] * 36 + sq[k] * 4) << 2),
                      Vb4[sarr[k]] + ((nd * 8 + srr[k]) * 256 + (c + 1) * 16 + kh * 8 + sq[k]));
            CPA_COMMIT();
            CPA_WAIT1();
        } else {
            CPA_WAIT0();
        }
        __syncwarp();

        const uint32_t* VH = Wbuf + buf * 576;
        const uint32_t* VL = VH + 288;

        #pragma unroll
        for (int kk = 0; kk < 4; ++kk) {
            float* cacc = (kk & 1) ? cacc1 : cacc0;
            const int kp = kh * 4 + kk;
            const int k0 = (c << 7) + (kp << 4);
            uint2 A0 = *(uint2*)&sc_u[gid * RS + k0 + 2 * tig];
            uint2 A1 = *(uint2*)&sc_u[(gid + 8) * RS + k0 + 2 * tig];
            uint2 A2 = *(uint2*)&sc_u[gid * RS + k0 + 8 + 2 * tig];
            uint2 A3 = *(uint2*)&sc_u[(gid + 8) * RS + k0 + 8 + 2 * tig];
            uint32_t ah[4] = {A0.x, A1.x, A2.x, A3.x};
            uint32_t al[4] = {A0.y, A1.y, A2.y, A3.y};

            uint32_t b0h = VH[gid * 36 + kk * 8 + tig];
            uint32_t b1h = VH[gid * 36 + kk * 8 + 4 + tig];
            uint32_t b0l = VL[gid * 36 + kk * 8 + tig];
            uint32_t b1l = VL[gid * 36 + kk * 8 + 4 + tig];
            mma_bf16(cacc, ah, b0h, b1h);
            mma_bf16(cacc, ah, b0l, b1l);
            mma_bf16(cacc, al, b0h, b1h);
        }
        __syncwarp();
    }

    // ---- partials into own slice, reduce across kh, write g_O ----
    {
        float* PS = (float*)(ST + w * WSL);
        PS[gid * 8 + 2 * tig]           = cacc0[0] + cacc1[0];
        PS[gid * 8 + 2 * tig + 1]       = cacc0[1] + cacc1[1];
        PS[(gid + 8) * 8 + 2 * tig]     = cacc0[2] + cacc1[2];
        PS[(gid + 8) * 8 + 2 * tig + 1] = cacc0[3] + cacc1[3];
    }
    __syncthreads();

    {
        const float* PSb = (const float*)ST;
        for (int i = tid; i < TM * Dq; i += 512) {
            int r = i >> 6, d = i & 63;
            int n2 = d >> 3, dd = d & 7;
            float o = (PSb[(size_t)n2 * WSL + r * 8 + dd] +
                       PSb[(size_t)(8 + n2) * WSL + r * 8 + dd]) * inv[r];
            g_O[((size_t)(b * Sq + t0 + r)) * Eq + h * Dq + d] = o;
        }
    }
}

// ---------------------------------------------------------------------------
// Launch
// ---------------------------------------------------------------------------
extern "C" void kernel_launch(void* const* d_in, const int* in_sizes, int n_in,
                              void* d_out, int out_size)
{
    const float* query = (const float*)d_in[0];
    const float* key   = (const float*)d_in[1];
    const float* value = (const float*)d_in[2];
    const float* Wq    = (const float*)d_in[3];
    const float* bq    = (const float*)d_in[4];
    const float* Wk    = (const float*)d_in[5];
    const float* bk    = (const float*)d_in[6];
    const float* Wv    = (const float*)d_in[7];
    const float* bv    = (const float*)d_in[8];
    const float* Wo    = (const float*)d_in[9];
    const float* bo    = (const float*)d_in[10];
    const float* ts    = (const float*)d_in[11];

    cudaFuncSetAttribute(attn_kernel, cudaFuncAttributeMaxDynamicSharedMemorySize,
                         SMEM_FLOATS * 4);

    dim3 gT(Eq / 32, Eq / 32, 4);
    wtrans_kernel<<<gT, dim3(32, 8)>>>(Wq, Wk, Wv, Wo);

    float* wt; cudaGetSymbolAddress((void**)&wt, g_Wt);

    dim3 gQKV(Eq / 128, (Bq * Sq) / 128, 3);
    gemm_qkv_kernel<<<gQKV, 256>>>(query, key, value, wt, bq, bk, bv, ts);

    conv_v_kernel<<<8192, 256>>>();

    dim3 gAttn(Sq / TM, Bq * Hq);
    attn_kernel<<<gAttn, 512, SMEM_FLOATS * 4>>>();

    dim3 gO(Eq / 128, (Bq * Sq) / 128);
    gemm_out_kernel<<<gO, 256>>>(wt, bo, (float*)d_out);
}